// round 2
// baseline (speedup 1.0000x reference)
#include <cuda_runtime.h>
#include <math.h>
#include <stdint.h>

#define D     1024
#define HD    4096
#define NE    8
#define TOPK  2
#define MAXT  8192
#define MAXROWS (MAXT * TOPK)
#define TM    128
#define TN    128
#define KT    16
#define LN_EPS 1e-5f

// ---------------- scratch (static device globals; no allocation) ------------
__device__ float g_xn[(size_t)MAXT * D];        // 32 MB  normalized tokens
__device__ float g_h1[(size_t)MAXROWS * HD];    // 256 MB GEMM1 output (gelu'd)
__device__ float g_y [(size_t)MAXROWS * D];     // 64 MB  per-slot weighted expert out
__device__ float g_wts[MAXROWS];
__device__ int   g_sel[MAXROWS];
__device__ int   g_rowmap[MAXROWS];
__device__ int   g_counts[NE];
__device__ int   g_offsets[NE + 1];
__device__ int   g_cursor[NE];

// ---------------- f32x2 packed math helpers (sm_100+) -----------------------
__device__ __forceinline__ unsigned long long pack2(float lo, float hi) {
    unsigned long long r;
    asm("mov.b64 %0, {%1, %2};" : "=l"(r) : "f"(lo), "f"(hi));
    return r;
}
__device__ __forceinline__ float2 unpack2(unsigned long long v) {
    float2 r;
    asm("mov.b64 {%0, %1}, %2;" : "=f"(r.x), "=f"(r.y) : "l"(v));
    return r;
}
__device__ __forceinline__ void fma2(unsigned long long &d,
                                     unsigned long long a,
                                     unsigned long long b) {
    asm("fma.rn.f32x2 %0, %1, %2, %0;" : "+l"(d) : "l"(a), "l"(b));
}

// ---------------- kernel 0: zero expert counts ------------------------------
__global__ void init_kernel() {
    if (threadIdx.x < NE) g_counts[threadIdx.x] = 0;
}

// ---------------- kernel 1: gating + layernorm ------------------------------
// one block (256 threads) per token
__global__ __launch_bounds__(256) void gate_ln_kernel(
    const float* __restrict__ x, const float* __restrict__ gw)
{
    const int t   = blockIdx.x;
    const int tid = threadIdx.x;

    __shared__ float sh_ws[8], sh_wq[8], sh_wl[8][8];
    __shared__ float sh_mu, sh_rstd;

    const float4 xv = reinterpret_cast<const float4*>(x + (size_t)t * D)[tid];
    float s = xv.x + xv.y + xv.z + xv.w;
    float q = xv.x * xv.x + xv.y * xv.y + xv.z * xv.z + xv.w * xv.w;

    float acc[8];
#pragma unroll
    for (int e = 0; e < 8; e++) acc[e] = 0.f;

    const float xs[4] = {xv.x, xv.y, xv.z, xv.w};
#pragma unroll
    for (int j = 0; j < 4; j++) {
        const int d = tid * 4 + j;
        const float4 g0 = *reinterpret_cast<const float4*>(gw + (size_t)d * 8);
        const float4 g1 = *reinterpret_cast<const float4*>(gw + (size_t)d * 8 + 4);
        const float xj = xs[j];
        acc[0] = fmaf(xj, g0.x, acc[0]); acc[1] = fmaf(xj, g0.y, acc[1]);
        acc[2] = fmaf(xj, g0.z, acc[2]); acc[3] = fmaf(xj, g0.w, acc[3]);
        acc[4] = fmaf(xj, g1.x, acc[4]); acc[5] = fmaf(xj, g1.y, acc[5]);
        acc[6] = fmaf(xj, g1.z, acc[6]); acc[7] = fmaf(xj, g1.w, acc[7]);
    }

#pragma unroll
    for (int o = 16; o > 0; o >>= 1) {
        s += __shfl_xor_sync(0xffffffffu, s, o);
        q += __shfl_xor_sync(0xffffffffu, q, o);
#pragma unroll
        for (int e = 0; e < 8; e++)
            acc[e] += __shfl_xor_sync(0xffffffffu, acc[e], o);
    }
    const int wid = tid >> 5, lane = tid & 31;
    if (lane == 0) {
        sh_ws[wid] = s; sh_wq[wid] = q;
#pragma unroll
        for (int e = 0; e < 8; e++) sh_wl[wid][e] = acc[e];
    }
    __syncthreads();

    if (tid == 0) {
        float S = 0.f, Q = 0.f, L[8];
#pragma unroll
        for (int e = 0; e < 8; e++) L[e] = 0.f;
        for (int w = 0; w < 8; w++) {
            S += sh_ws[w]; Q += sh_wq[w];
#pragma unroll
            for (int e = 0; e < 8; e++) L[e] += sh_wl[w][e];
        }
        const float mu  = S * (1.f / (float)D);
        float var = Q * (1.f / (float)D) - mu * mu;
        if (var < 0.f) var = 0.f;
        sh_mu = mu;
        sh_rstd = rsqrtf(var + LN_EPS);

        // softmax over logits
        float mx = L[0];
#pragma unroll
        for (int e = 1; e < 8; e++) mx = fmaxf(mx, L[e]);
        float p[8], se = 0.f;
#pragma unroll
        for (int e = 0; e < 8; e++) { p[e] = expf(L[e] - mx); se += p[e]; }
        const float inv = 1.f / se;
#pragma unroll
        for (int e = 0; e < 8; e++) p[e] *= inv;

        // top-2 (ties -> lower index, matching jax top_k)
        int i0 = 0; float p0 = p[0];
#pragma unroll
        for (int e = 1; e < 8; e++) if (p[e] > p0) { p0 = p[e]; i0 = e; }
        int i1 = -1; float p1 = -1e30f;
#pragma unroll
        for (int e = 0; e < 8; e++)
            if (e != i0 && p[e] > p1) { p1 = p[e]; i1 = e; }

        // softmax over the two selected probability values
        const float ew = expf(p1 - p0);
        const float w0 = 1.f / (1.f + ew);
        const float w1v = ew / (1.f + ew);

        g_sel[2 * t]     = i0;  g_sel[2 * t + 1] = i1;
        g_wts[2 * t]     = w0;  g_wts[2 * t + 1] = w1v;
        atomicAdd(&g_counts[i0], 1);
        atomicAdd(&g_counts[i1], 1);
    }
    __syncthreads();

    const float mu = sh_mu, rstd = sh_rstd;
    float4 xn;
    xn.x = (xv.x - mu) * rstd; xn.y = (xv.y - mu) * rstd;
    xn.z = (xv.z - mu) * rstd; xn.w = (xv.w - mu) * rstd;
    reinterpret_cast<float4*>(g_xn + (size_t)t * D)[tid] = xn;
}

// ---------------- kernel 2: prefix offsets ----------------------------------
__global__ void offsets_kernel() {
    if (threadIdx.x == 0) {
        int o = 0;
        for (int e = 0; e < NE; e++) {
            g_offsets[e] = o;
            g_cursor[e]  = o;
            o += g_counts[e];
        }
        g_offsets[NE] = o;
    }
}

// ---------------- kernel 3: scatter assignments to expert segments ----------
__global__ void scatter_kernel(int total) {
    const int i = blockIdx.x * blockDim.x + threadIdx.x;
    if (i < total) {
        const int e = g_sel[i];
        const int pos = atomicAdd(&g_cursor[e], 1);
        g_rowmap[pos] = i;
    }
}

// ---------------- kernel 4: grouped GEMM1 + bias + exact GELU ---------------
// h1[row, :] = gelu( (xn[tok]*ln_s[e]+ln_b[e]) @ W1[e] + b1[e] )
__global__ __launch_bounds__(256) void gemm1_kernel(
    const float* __restrict__ w1, const float* __restrict__ b1,
    const float* __restrict__ ln_scale, const float* __restrict__ ln_bias)
{
    const int e    = blockIdx.z;
    const int seg0 = g_offsets[e];
    const int nseg = g_offsets[e + 1] - seg0;
    const int m0   = blockIdx.y * TM;
    if (m0 >= nseg) return;
    const int n0   = blockIdx.x * TN;

    __shared__ float As[KT][TM];   // transposed [k][m]
    __shared__ float Bs[KT][TN];

    const int tid  = threadIdx.x;
    const int la_m = tid >> 1;
    const int la_k = (tid & 1) * 8;
    const bool av  = (m0 + la_m) < nseg;
    int tok = 0;
    if (av) tok = g_rowmap[seg0 + m0 + la_m] >> 1;
    const float* xrow = g_xn + (size_t)tok * D;
    const float* lns  = ln_scale + (size_t)e * D;
    const float* lnb  = ln_bias  + (size_t)e * D;

    const int lb_k = tid >> 4;
    const int lb_n = (tid & 15) * 8;

    const int tx = tid & 15;   // n microtile
    const int ty = tid >> 4;   // m microtile

    unsigned long long accq[8][4];
#pragma unroll
    for (int i = 0; i < 8; i++)
#pragma unroll
        for (int j = 0; j < 4; j++) accq[i][j] = 0ULL;

    auto loadA = [&](int kt, float v[8]) {
        const int kk = kt + la_k;
        const float4 s0 = *reinterpret_cast<const float4*>(lns + kk);
        const float4 s1 = *reinterpret_cast<const float4*>(lns + kk + 4);
        const float4 c0 = *reinterpret_cast<const float4*>(lnb + kk);
        const float4 c1 = *reinterpret_cast<const float4*>(lnb + kk + 4);
        float4 x0 = make_float4(0.f, 0.f, 0.f, 0.f), x1 = x0;
        if (av) {
            x0 = *reinterpret_cast<const float4*>(xrow + kk);
            x1 = *reinterpret_cast<const float4*>(xrow + kk + 4);
        }
        float t0 = fmaf(x0.x, s0.x, c0.x), t1 = fmaf(x0.y, s0.y, c0.y);
        float t2 = fmaf(x0.z, s0.z, c0.z), t3 = fmaf(x0.w, s0.w, c0.w);
        float t4 = fmaf(x1.x, s1.x, c1.x), t5 = fmaf(x1.y, s1.y, c1.y);
        float t6 = fmaf(x1.z, s1.z, c1.z), t7 = fmaf(x1.w, s1.w, c1.w);
        v[0] = av ? t0 : 0.f; v[1] = av ? t1 : 0.f;
        v[2] = av ? t2 : 0.f; v[3] = av ? t3 : 0.f;
        v[4] = av ? t4 : 0.f; v[5] = av ? t5 : 0.f;
        v[6] = av ? t6 : 0.f; v[7] = av ? t7 : 0.f;
    };
    auto loadB = [&](int kt, float v[8]) {
        const float* bp = w1 + ((size_t)e * D + kt + lb_k) * HD + n0 + lb_n;
        const float4 t0 = *reinterpret_cast<const float4*>(bp);
        const float4 t1 = *reinterpret_cast<const float4*>(bp + 4);
        v[0] = t0.x; v[1] = t0.y; v[2] = t0.z; v[3] = t0.w;
        v[4] = t1.x; v[5] = t1.y; v[6] = t1.z; v[7] = t1.w;
    };
    auto stsAB = [&](const float va[8], const float vb[8]) {
#pragma unroll
        for (int j = 0; j < 8; j++) As[la_k + j][la_m] = va[j];
        *reinterpret_cast<float4*>(&Bs[lb_k][lb_n]) =
            make_float4(vb[0], vb[1], vb[2], vb[3]);
        *reinterpret_cast<float4*>(&Bs[lb_k][lb_n + 4]) =
            make_float4(vb[4], vb[5], vb[6], vb[7]);
    };

    float ra[8], rb[8];
    loadA(0, ra); loadB(0, rb);

    for (int kt = 0; kt < D; kt += KT) {
        stsAB(ra, rb);
        __syncthreads();
        if (kt + KT < D) { loadA(kt + KT, ra); loadB(kt + KT, rb); }
#pragma unroll
        for (int k = 0; k < KT; k++) {
            float a[8];
            *reinterpret_cast<float4*>(&a[0]) =
                *reinterpret_cast<const float4*>(&As[k][ty * 8]);
            *reinterpret_cast<float4*>(&a[4]) =
                *reinterpret_cast<const float4*>(&As[k][ty * 8 + 4]);
            const unsigned long long* brow =
                reinterpret_cast<const unsigned long long*>(&Bs[k][tx * 8]);
            unsigned long long bq0 = brow[0], bq1 = brow[1],
                               bq2 = brow[2], bq3 = brow[3];
#pragma unroll
            for (int i = 0; i < 8; i++) {
                const unsigned long long ap = pack2(a[i], a[i]);
                fma2(accq[i][0], ap, bq0);
                fma2(accq[i][1], ap, bq1);
                fma2(accq[i][2], ap, bq2);
                fma2(accq[i][3], ap, bq3);
            }
        }
        __syncthreads();
    }

    // epilogue: +b1, exact GELU, store h1
    float bb[8];
    {
        const float4 b0 = *reinterpret_cast<const float4*>(b1 + (size_t)e * HD + n0 + tx * 8);
        const float4 b4 = *reinterpret_cast<const float4*>(b1 + (size_t)e * HD + n0 + tx * 8 + 4);
        bb[0] = b0.x; bb[1] = b0.y; bb[2] = b0.z; bb[3] = b0.w;
        bb[4] = b4.x; bb[5] = b4.y; bb[6] = b4.z; bb[7] = b4.w;
    }
#pragma unroll
    for (int i = 0; i < 8; i++) {
        const int m = m0 + ty * 8 + i;
        if (m >= nseg) continue;
        const size_t rowbase = (size_t)(seg0 + m) * HD;
#pragma unroll
        for (int j = 0; j < 4; j++) {
            const float2 f = unpack2(accq[i][j]);
            const int n = n0 + tx * 8 + j * 2;
            float y0 = f.x + bb[j * 2];
            float y1 = f.y + bb[j * 2 + 1];
            y0 = 0.5f * y0 * (1.f + erff(y0 * 0.70710678118654752f));
            y1 = 0.5f * y1 * (1.f + erff(y1 * 0.70710678118654752f));
            *reinterpret_cast<float2*>(&g_h1[rowbase + n]) = make_float2(y0, y1);
        }
    }
}

// ---------------- kernel 5: grouped GEMM2 + bias + combine weight -----------
// y[slot, :] = wts[slot] * ( h1[row, :] @ W2[e] + b2[e] )
__global__ __launch_bounds__(256) void gemm2_kernel(
    const float* __restrict__ w2, const float* __restrict__ b2)
{
    const int e    = blockIdx.z;
    const int seg0 = g_offsets[e];
    const int nseg = g_offsets[e + 1] - seg0;
    const int m0   = blockIdx.y * TM;
    if (m0 >= nseg) return;
    const int n0   = blockIdx.x * TN;

    __shared__ float As[KT][TM];
    __shared__ float Bs[KT][TN];

    const int tid  = threadIdx.x;
    const int la_m = tid >> 1;
    const int la_k = (tid & 1) * 8;
    const bool av  = (m0 + la_m) < nseg;
    const float* arow = g_h1 + (size_t)(av ? (seg0 + m0 + la_m) : 0) * HD;

    const int lb_k = tid >> 4;
    const int lb_n = (tid & 15) * 8;
    const int tx = tid & 15;
    const int ty = tid >> 4;

    unsigned long long accq[8][4];
#pragma unroll
    for (int i = 0; i < 8; i++)
#pragma unroll
        for (int j = 0; j < 4; j++) accq[i][j] = 0ULL;

    auto loadA = [&](int kt, float v[8]) {
        float4 x0 = make_float4(0.f, 0.f, 0.f, 0.f), x1 = x0;
        if (av) {
            x0 = *reinterpret_cast<const float4*>(arow + kt + la_k);
            x1 = *reinterpret_cast<const float4*>(arow + kt + la_k + 4);
        }
        v[0] = x0.x; v[1] = x0.y; v[2] = x0.z; v[3] = x0.w;
        v[4] = x1.x; v[5] = x1.y; v[6] = x1.z; v[7] = x1.w;
    };
    auto loadB = [&](int kt, float v[8]) {
        const float* bp = w2 + ((size_t)e * HD + kt + lb_k) * D + n0 + lb_n;
        const float4 t0 = *reinterpret_cast<const float4*>(bp);
        const float4 t1 = *reinterpret_cast<const float4*>(bp + 4);
        v[0] = t0.x; v[1] = t0.y; v[2] = t0.z; v[3] = t0.w;
        v[4] = t1.x; v[5] = t1.y; v[6] = t1.z; v[7] = t1.w;
    };
    auto stsAB = [&](const float va[8], const float vb[8]) {
#pragma unroll
        for (int j = 0; j < 8; j++) As[la_k + j][la_m] = va[j];
        *reinterpret_cast<float4*>(&Bs[lb_k][lb_n]) =
            make_float4(vb[0], vb[1], vb[2], vb[3]);
        *reinterpret_cast<float4*>(&Bs[lb_k][lb_n + 4]) =
            make_float4(vb[4], vb[5], vb[6], vb[7]);
    };

    float ra[8], rb[8];
    loadA(0, ra); loadB(0, rb);

    for (int kt = 0; kt < HD; kt += KT) {
        stsAB(ra, rb);
        __syncthreads();
        if (kt + KT < HD) { loadA(kt + KT, ra); loadB(kt + KT, rb); }
#pragma unroll
        for (int k = 0; k < KT; k++) {
            float a[8];
            *reinterpret_cast<float4*>(&a[0]) =
                *reinterpret_cast<const float4*>(&As[k][ty * 8]);
            *reinterpret_cast<float4*>(&a[4]) =
                *reinterpret_cast<const float4*>(&As[k][ty * 8 + 4]);
            const unsigned long long* brow =
                reinterpret_cast<const unsigned long long*>(&Bs[k][tx * 8]);
            unsigned long long bq0 = brow[0], bq1 = brow[1],
                               bq2 = brow[2], bq3 = brow[3];
#pragma unroll
            for (int i = 0; i < 8; i++) {
                const unsigned long long ap = pack2(a[i], a[i]);
                fma2(accq[i][0], ap, bq0);
                fma2(accq[i][1], ap, bq1);
                fma2(accq[i][2], ap, bq2);
                fma2(accq[i][3], ap, bq3);
            }
        }
        __syncthreads();
    }

    float bb[8];
    {
        const float4 b0 = *reinterpret_cast<const float4*>(b2 + (size_t)e * D + n0 + tx * 8);
        const float4 b4 = *reinterpret_cast<const float4*>(b2 + (size_t)e * D + n0 + tx * 8 + 4);
        bb[0] = b0.x; bb[1] = b0.y; bb[2] = b0.z; bb[3] = b0.w;
        bb[4] = b4.x; bb[5] = b4.y; bb[6] = b4.z; bb[7] = b4.w;
    }
#pragma unroll
    for (int i = 0; i < 8; i++) {
        const int m = m0 + ty * 8 + i;
        if (m >= nseg) continue;
        const int grow = seg0 + m;
        const int slot = g_rowmap[grow];
        const float wt = g_wts[slot];
        const size_t ob = (size_t)slot * D;
#pragma unroll
        for (int j = 0; j < 4; j++) {
            const float2 f = unpack2(accq[i][j]);
            const int n = n0 + tx * 8 + j * 2;
            const float v0 = (f.x + bb[j * 2]) * wt;
            const float v1 = (f.y + bb[j * 2 + 1]) * wt;
            *reinterpret_cast<float2*>(&g_y[ob + n]) = make_float2(v0, v1);
        }
    }
}

// ---------------- kernel 6: combine the two expert slots per token ----------
__global__ void combine_kernel(float* __restrict__ out, int T) {
    const int nd4 = D / 4;
    const int i = blockIdx.x * blockDim.x + threadIdx.x;
    if (i >= T * nd4) return;
    const int t = i / nd4, d4 = i % nd4;
    const float4* y4 = reinterpret_cast<const float4*>(g_y);
    const float4 a = y4[(size_t)(2 * t) * nd4 + d4];
    const float4 b = y4[(size_t)(2 * t + 1) * nd4 + d4];
    reinterpret_cast<float4*>(out)[i] =
        make_float4(a.x + b.x, a.y + b.y, a.z + b.z, a.w + b.w);
}

// ---------------- launch ----------------------------------------------------
extern "C" void kernel_launch(void* const* d_in, const int* in_sizes, int n_in,
                              void* d_out, int out_size)
{
    const float* x   = (const float*)d_in[0];
    const float* gw  = (const float*)d_in[1];
    const float* lns = (const float*)d_in[2];
    const float* lnb = (const float*)d_in[3];
    const float* w1  = (const float*)d_in[4];
    const float* b1  = (const float*)d_in[5];
    const float* w2  = (const float*)d_in[6];
    const float* b2  = (const float*)d_in[7];
    float* out = (float*)d_out;

    const int T = in_sizes[0] / D;   // 8192
    const int totalRows = T * TOPK;  // 16384

    init_kernel<<<1, 32>>>();
    gate_ln_kernel<<<T, 256>>>(x, gw);
    offsets_kernel<<<1, 32>>>();
    scatter_kernel<<<(totalRows + 255) / 256, 256>>>(totalRows);

    dim3 g1(HD / TN, (totalRows + TM - 1) / TM, NE);
    gemm1_kernel<<<g1, 256>>>(w1, b1, lns, lnb);

    dim3 g2(D / TN, (totalRows + TM - 1) / TM, NE);
    gemm2_kernel<<<g2, 256>>>(w2, b2);

    combine_kernel<<<(T * (D / 4) + 255) / 256, 256>>>(out, T);
}

// round 4
// speedup vs baseline: 1.4748x; 1.4748x over previous
#include <cuda_runtime.h>
#include <cuda_bf16.h>
#include <math.h>
#include <stdint.h>

#define D     1024
#define HD    4096
#define NE    8
#define TOPK  2
#define MAXT  8192
#define MAXROWS (MAXT * TOPK)
#define LN_EPS 1e-5f

// GEMM tiling
#define TM 128
#define TN 128
#define KC 64                        // 64 bf16 per row = 128B = SW128 atom
#define TB 16384                     // one 128x64 bf16 tile
#define BUFB (4 * TB)                // Ahi, Alo, Bhi, Blo
#define SMEM_BYTES (2 * BUFB)        // 131072 double-buffered
#define NTH 640                      // 512 compute + 128 producer threads

// ---------------- scratch ----------------------------------------------------
__device__ float g_xn[(size_t)MAXT * D];
__device__ float g_h1[(size_t)MAXROWS * HD];
__device__ float g_y [(size_t)MAXROWS * D];
__device__ float g_wts[MAXROWS];
__device__ int   g_sel[MAXROWS];
__device__ int   g_rowmap[MAXROWS];
__device__ int   g_counts[NE];
__device__ int   g_offsets[NE + 1];
__device__ int   g_cursor[NE];

// ---------------- helpers ----------------------------------------------------
__device__ __forceinline__ uint32_t smem_u32(const void* p) {
    uint32_t a;
    asm("{ .reg .u64 t; cvta.to.shared.u64 t, %1; cvt.u32.u64 %0, t; }"
        : "=r"(a) : "l"(p));
    return a;
}
#define SWZ(o) ((o) ^ (((o) >> 3) & 0x70))

#define LDM4(r0, r1, r2, r3, addr) \
    asm volatile("ldmatrix.sync.aligned.m8n8.x4.shared.b16 {%0,%1,%2,%3}, [%4];" \
        : "=r"(r0), "=r"(r1), "=r"(r2), "=r"(r3) : "r"(addr))

#define MMA16816(c, a, b) \
    asm volatile("mma.sync.aligned.m16n8k16.row.col.f32.bf16.bf16.f32 " \
        "{%0,%1,%2,%3}, {%4,%5,%6,%7}, {%8,%9}, {%0,%1,%2,%3};" \
        : "+f"((c)[0]), "+f"((c)[1]), "+f"((c)[2]), "+f"((c)[3]) \
        : "r"((a)[0]), "r"((a)[1]), "r"((a)[2]), "r"((a)[3]), \
          "r"((b)[0]), "r"((b)[1]))

__device__ __forceinline__ uint32_t pack_bf2(float a, float b) {
    __nv_bfloat162 h = __floats2bfloat162_rn(a, b);
    return *reinterpret_cast<uint32_t*>(&h);
}
__device__ __forceinline__ void split8(const float v[8], uint4 &hi, uint4 &lo) {
    float h[8], l[8];
#pragma unroll
    for (int j = 0; j < 8; j++) {
        __nv_bfloat16 hb = __float2bfloat16_rn(v[j]);
        h[j] = __bfloat162float(hb);
        l[j] = v[j] - h[j];
    }
    hi = make_uint4(pack_bf2(h[0], h[1]), pack_bf2(h[2], h[3]),
                    pack_bf2(h[4], h[5]), pack_bf2(h[6], h[7]));
    lo = make_uint4(pack_bf2(l[0], l[1]), pack_bf2(l[2], l[3]),
                    pack_bf2(l[4], l[5]), pack_bf2(l[6], l[7]));
}

// ---------------- routing ----------------------------------------------------
__global__ void init_kernel() {
    if (threadIdx.x < NE) g_counts[threadIdx.x] = 0;
}

__global__ __launch_bounds__(256) void gate_ln_kernel(
    const float* __restrict__ x, const float* __restrict__ gw)
{
    const int t   = blockIdx.x;
    const int tid = threadIdx.x;
    __shared__ float sh_ws[8], sh_wq[8], sh_wl[8][8];
    __shared__ float sh_mu, sh_rstd;

    const float4 xv = reinterpret_cast<const float4*>(x + (size_t)t * D)[tid];
    float s = xv.x + xv.y + xv.z + xv.w;
    float q = xv.x * xv.x + xv.y * xv.y + xv.z * xv.z + xv.w * xv.w;

    float acc[8];
#pragma unroll
    for (int e = 0; e < 8; e++) acc[e] = 0.f;
    const float xs[4] = {xv.x, xv.y, xv.z, xv.w};
#pragma unroll
    for (int j = 0; j < 4; j++) {
        const int d = tid * 4 + j;
        const float4 g0 = *reinterpret_cast<const float4*>(gw + (size_t)d * 8);
        const float4 g1 = *reinterpret_cast<const float4*>(gw + (size_t)d * 8 + 4);
        const float xj = xs[j];
        acc[0] = fmaf(xj, g0.x, acc[0]); acc[1] = fmaf(xj, g0.y, acc[1]);
        acc[2] = fmaf(xj, g0.z, acc[2]); acc[3] = fmaf(xj, g0.w, acc[3]);
        acc[4] = fmaf(xj, g1.x, acc[4]); acc[5] = fmaf(xj, g1.y, acc[5]);
        acc[6] = fmaf(xj, g1.z, acc[6]); acc[7] = fmaf(xj, g1.w, acc[7]);
    }
#pragma unroll
    for (int o = 16; o > 0; o >>= 1) {
        s += __shfl_xor_sync(0xffffffffu, s, o);
        q += __shfl_xor_sync(0xffffffffu, q, o);
#pragma unroll
        for (int e = 0; e < 8; e++)
            acc[e] += __shfl_xor_sync(0xffffffffu, acc[e], o);
    }
    const int wid = tid >> 5, lane = tid & 31;
    if (lane == 0) {
        sh_ws[wid] = s; sh_wq[wid] = q;
#pragma unroll
        for (int e = 0; e < 8; e++) sh_wl[wid][e] = acc[e];
    }
    __syncthreads();

    if (tid == 0) {
        float S = 0.f, Q = 0.f, L[8];
#pragma unroll
        for (int e = 0; e < 8; e++) L[e] = 0.f;
        for (int w = 0; w < 8; w++) {
            S += sh_ws[w]; Q += sh_wq[w];
#pragma unroll
            for (int e = 0; e < 8; e++) L[e] += sh_wl[w][e];
        }
        const float mu = S * (1.f / (float)D);
        float var = Q * (1.f / (float)D) - mu * mu;
        if (var < 0.f) var = 0.f;
        sh_mu = mu; sh_rstd = rsqrtf(var + LN_EPS);

        float mx = L[0];
#pragma unroll
        for (int e = 1; e < 8; e++) mx = fmaxf(mx, L[e]);
        float p[8], se = 0.f;
#pragma unroll
        for (int e = 0; e < 8; e++) { p[e] = expf(L[e] - mx); se += p[e]; }
        const float inv = 1.f / se;
#pragma unroll
        for (int e = 0; e < 8; e++) p[e] *= inv;

        int i0 = 0; float p0 = p[0];
#pragma unroll
        for (int e = 1; e < 8; e++) if (p[e] > p0) { p0 = p[e]; i0 = e; }
        int i1 = -1; float p1 = -1e30f;
#pragma unroll
        for (int e = 0; e < 8; e++)
            if (e != i0 && p[e] > p1) { p1 = p[e]; i1 = e; }

        const float ew = expf(p1 - p0);
        g_sel[2 * t] = i0;  g_sel[2 * t + 1] = i1;
        g_wts[2 * t] = 1.f / (1.f + ew);
        g_wts[2 * t + 1] = ew / (1.f + ew);
        atomicAdd(&g_counts[i0], 1);
        atomicAdd(&g_counts[i1], 1);
    }
    __syncthreads();

    const float mu = sh_mu, rstd = sh_rstd;
    float4 xn;
    xn.x = (xv.x - mu) * rstd; xn.y = (xv.y - mu) * rstd;
    xn.z = (xv.z - mu) * rstd; xn.w = (xv.w - mu) * rstd;
    reinterpret_cast<float4*>(g_xn + (size_t)t * D)[tid] = xn;
}

__global__ void offsets_kernel() {
    if (threadIdx.x == 0) {
        int o = 0;
        for (int e = 0; e < NE; e++) {
            g_offsets[e] = o; g_cursor[e] = o; o += g_counts[e];
        }
        g_offsets[NE] = o;
    }
}

__global__ void scatter_kernel(int total) {
    const int i = blockIdx.x * blockDim.x + threadIdx.x;
    if (i < total) {
        const int e = g_sel[i];
        const int pos = atomicAdd(&g_cursor[e], 1);
        g_rowmap[pos] = i;
    }
}

// ---------------- warp-specialized mma.sync grouped GEMM ---------------------
// G1: h1[row,:] = gelu((xn[tok]*lns+lnb) @ W1[e] + b1[e])   KTOT=D,  NTOT=HD
// G2: y[slot,:] = wts[slot] * (h1[row,:] @ W2[e] + b2[e])   KTOT=HD, NTOT=D
template<bool G1>
__global__ __launch_bounds__(NTH, 1) void gemm_mma(
    const float* __restrict__ W, const float* __restrict__ bias,
    const float* __restrict__ lns_, const float* __restrict__ lnb_)
{
    constexpr int KTOT = G1 ? D : HD;
    constexpr int NTOT = G1 ? HD : D;
    constexpr int NC   = KTOT / KC;

    const int e    = blockIdx.z;
    const int seg0 = g_offsets[e];
    const int nseg = g_offsets[e + 1] - seg0;
    const int m0   = blockIdx.y * TM;
    if (m0 >= nseg) return;
    const int n0   = blockIdx.x * TN;

    extern __shared__ __align__(1024) char smem[];
    const uint32_t sb = smem_u32(smem);
    const int tid = threadIdx.x;
    const bool prod = tid >= 512;

    // ---- producer state ----
    const int ptid  = prod ? (tid - 512) : 0;
    const int tlane = ptid & 7;     // k-octet within row
    const int trow  = ptid >> 3;    // 0..15
    int  rowA[8]; bool valA[8];
#pragma unroll
    for (int p = 0; p < 8; p++) {
        const int m = p * 16 + trow;
        valA[p] = prod && ((m0 + m) < nseg);
        if (G1) rowA[p] = valA[p] ? (g_rowmap[seg0 + m0 + m] >> 1) : 0;
        else    rowA[p] = valA[p] ? (seg0 + m0 + m) : 0;
    }

    auto fill = [&](int buf, int c) {
        char* bp = smem + buf * BUFB;
        const int kb = c * KC;
        const int kcol = tlane * 8;
        // A tile 128x64
#pragma unroll
        for (int p = 0; p < 8; p++) {
            float v[8];
            if (valA[p]) {
                const float* src = (G1 ? g_xn + (size_t)rowA[p] * D
                                       : g_h1 + (size_t)rowA[p] * HD) + kb + kcol;
                const float4 a0 = *reinterpret_cast<const float4*>(src);
                const float4 a1 = *reinterpret_cast<const float4*>(src + 4);
                v[0]=a0.x; v[1]=a0.y; v[2]=a0.z; v[3]=a0.w;
                v[4]=a1.x; v[5]=a1.y; v[6]=a1.z; v[7]=a1.w;
                if (G1) {
                    const float* sp = lns_ + (size_t)e * D + kb + kcol;
                    const float* cp = lnb_ + (size_t)e * D + kb + kcol;
                    const float4 s0 = *reinterpret_cast<const float4*>(sp);
                    const float4 s1 = *reinterpret_cast<const float4*>(sp + 4);
                    const float4 c0 = *reinterpret_cast<const float4*>(cp);
                    const float4 c1 = *reinterpret_cast<const float4*>(cp + 4);
                    v[0]=fmaf(v[0],s0.x,c0.x); v[1]=fmaf(v[1],s0.y,c0.y);
                    v[2]=fmaf(v[2],s0.z,c0.z); v[3]=fmaf(v[3],s0.w,c0.w);
                    v[4]=fmaf(v[4],s1.x,c1.x); v[5]=fmaf(v[5],s1.y,c1.y);
                    v[6]=fmaf(v[6],s1.z,c1.z); v[7]=fmaf(v[7],s1.w,c1.w);
                }
            } else {
#pragma unroll
                for (int j = 0; j < 8; j++) v[j] = 0.f;
            }
            uint4 hi, lo;
            split8(v, hi, lo);
            const int m = p * 16 + trow;
            const uint32_t sw = SWZ((uint32_t)(m * 128 + tlane * 16));
            *reinterpret_cast<uint4*>(bp + 0 * TB + sw) = hi;
            *reinterpret_cast<uint4*>(bp + 1 * TB + sw) = lo;
        }
        // B tile: [n][k] transposed gather from W[k][n]
#pragma unroll
        for (int it = 0; it < 8; it++) {
            const int idx = it * 128 + ptid;
            const int n  = idx & 127;
            const int kg = idx >> 7;
            const float* wp = W + ((size_t)e * KTOT + kb + kg * 8) * NTOT + n0 + n;
            float v[8];
#pragma unroll
            for (int j = 0; j < 8; j++) v[j] = wp[(size_t)j * NTOT];
            uint4 hi, lo;
            split8(v, hi, lo);
            const uint32_t sw = SWZ((uint32_t)(n * 128 + kg * 16));
            *reinterpret_cast<uint4*>(bp + 2 * TB + sw) = hi;
            *reinterpret_cast<uint4*>(bp + 3 * TB + sw) = lo;
        }
    };

    // ---- consumer state ----
    const int wid    = tid >> 5;        // 0..15 compute
    const int lane   = tid & 31;
    const int warp_m = wid & 3;         // 4 x 32 rows
    const int warp_n = wid >> 2;        // 4 x 32 cols

    float acc[2][4][4];
#pragma unroll
    for (int i = 0; i < 2; i++)
#pragma unroll
        for (int j = 0; j < 4; j++)
#pragma unroll
            for (int k = 0; k < 4; k++) acc[i][j][k] = 0.f;

    const uint32_t sel    = (uint32_t)((lane & 7) << 4);
    const uint32_t rowAb  = (uint32_t)((warp_m * 32 + ((lane >> 3) & 1) * 8 + (lane & 7)) * 128);
    const uint32_t colA16 = (uint32_t)((lane >> 4) * 16);
    const uint32_t rowBb  = (uint32_t)((warp_n * 32 + (lane >> 4) * 8 + (lane & 7)) * 128);
    const uint32_t colB16 = (uint32_t)(((lane >> 3) & 1) * 16);

    auto compute = [&](int buf) {
        const uint32_t aH = sb + buf * BUFB;
        const uint32_t aL = aH + TB;
        const uint32_t bH = aH + 2 * TB;
        const uint32_t bL = aH + 3 * TB;
#pragma unroll
        for (int ks = 0; ks < 4; ks++) {
            const uint32_t colA = ((uint32_t)(ks * 32) + colA16) ^ sel;
            const uint32_t colB = ((uint32_t)(ks * 32) + colB16) ^ sel;
            uint32_t ah[2][4], al[2][4], bh[4][2], bl[4][2];
#pragma unroll
            for (int i = 0; i < 2; i++)
                LDM4(ah[i][0], ah[i][1], ah[i][2], ah[i][3],
                     aH + rowAb + (uint32_t)(i * 16 * 128) + colA);
#pragma unroll
            for (int j2 = 0; j2 < 2; j2++) {
                uint32_t t0, t1, t2, t3;
                LDM4(t0, t1, t2, t3, bH + rowBb + (uint32_t)(j2 * 16 * 128) + colB);
                bh[2*j2][0]=t0; bh[2*j2][1]=t1; bh[2*j2+1][0]=t2; bh[2*j2+1][1]=t3;
            }
#pragma unroll
            for (int i = 0; i < 2; i++)
#pragma unroll
                for (int j = 0; j < 4; j++) MMA16816(acc[i][j], ah[i], bh[j]);
#pragma unroll
            for (int j2 = 0; j2 < 2; j2++) {
                uint32_t t0, t1, t2, t3;
                LDM4(t0, t1, t2, t3, bL + rowBb + (uint32_t)(j2 * 16 * 128) + colB);
                bl[2*j2][0]=t0; bl[2*j2][1]=t1; bl[2*j2+1][0]=t2; bl[2*j2+1][1]=t3;
            }
#pragma unroll
            for (int i = 0; i < 2; i++)
#pragma unroll
                for (int j = 0; j < 4; j++) MMA16816(acc[i][j], ah[i], bl[j]);
#pragma unroll
            for (int i = 0; i < 2; i++)
                LDM4(al[i][0], al[i][1], al[i][2], al[i][3],
                     aL + rowAb + (uint32_t)(i * 16 * 128) + colA);
#pragma unroll
            for (int i = 0; i < 2; i++)
#pragma unroll
                for (int j = 0; j < 4; j++) MMA16816(acc[i][j], al[i], bh[j]);
        }
    };

    // ---- pipeline ----
    if (prod) fill(0, 0);
    __syncthreads();
    for (int c = 0; c < NC; c++) {
        if (prod) {
            if (c + 1 < NC) fill((c + 1) & 1, c + 1);
        } else {
            compute(c & 1);
        }
        __syncthreads();
    }

    // ---- epilogue (compute warps only) ----
    if (!prod) {
        const int r4 = lane >> 2;
        const int c2 = 2 * (lane & 3);
        const int nb = n0 + warp_n * 32;
        float2 bb[4];
#pragma unroll
        for (int j = 0; j < 4; j++)
            bb[j] = *reinterpret_cast<const float2*>(
                bias + (size_t)e * NTOT + nb + j * 8 + c2);
#pragma unroll
        for (int i = 0; i < 2; i++) {
#pragma unroll
            for (int h = 0; h < 2; h++) {
                const int mloc = warp_m * 32 + i * 16 + h * 8 + r4;
                if (m0 + mloc >= nseg) continue;
                if (G1) {
                    float* op = g_h1 + (size_t)(seg0 + m0 + mloc) * HD + nb;
#pragma unroll
                    for (int j = 0; j < 4; j++) {
                        float y0 = acc[i][j][2*h]   + bb[j].x;
                        float y1 = acc[i][j][2*h+1] + bb[j].y;
                        y0 = 0.5f * y0 * (1.f + erff(y0 * 0.70710678118654752f));
                        y1 = 0.5f * y1 * (1.f + erff(y1 * 0.70710678118654752f));
                        *reinterpret_cast<float2*>(op + j * 8 + c2) = make_float2(y0, y1);
                    }
                } else {
                    const int slot = g_rowmap[seg0 + m0 + mloc];
                    const float wt = g_wts[slot];
                    float* op = g_y + (size_t)slot * D + nb;
#pragma unroll
                    for (int j = 0; j < 4; j++) {
                        const float y0 = (acc[i][j][2*h]   + bb[j].x) * wt;
                        const float y1 = (acc[i][j][2*h+1] + bb[j].y) * wt;
                        *reinterpret_cast<float2*>(op + j * 8 + c2) = make_float2(y0, y1);
                    }
                }
            }
        }
    }
}

// ---------------- combine ----------------------------------------------------
__global__ void combine_kernel(float* __restrict__ out, int T) {
    const int nd4 = D / 4;
    const int i = blockIdx.x * blockDim.x + threadIdx.x;
    if (i >= T * nd4) return;
    const int t = i / nd4, d4 = i % nd4;
    const float4* y4 = reinterpret_cast<const float4*>(g_y);
    const float4 a = y4[(size_t)(2 * t) * nd4 + d4];
    const float4 b = y4[(size_t)(2 * t + 1) * nd4 + d4];
    reinterpret_cast<float4*>(out)[i] =
        make_float4(a.x + b.x, a.y + b.y, a.z + b.z, a.w + b.w);
}

// ---------------- launch -----------------------------------------------------
extern "C" void kernel_launch(void* const* d_in, const int* in_sizes, int n_in,
                              void* d_out, int out_size)
{
    const float* x   = (const float*)d_in[0];
    const float* gw  = (const float*)d_in[1];
    const float* lns = (const float*)d_in[2];
    const float* lnb = (const float*)d_in[3];
    const float* w1  = (const float*)d_in[4];
    const float* b1  = (const float*)d_in[5];
    const float* w2  = (const float*)d_in[6];
    const float* b2  = (const float*)d_in[7];
    float* out = (float*)d_out;

    const int T = in_sizes[0] / D;
    const int totalRows = T * TOPK;

    cudaFuncSetAttribute(gemm_mma<true>,
                         cudaFuncAttributeMaxDynamicSharedMemorySize, SMEM_BYTES);
    cudaFuncSetAttribute(gemm_mma<false>,
                         cudaFuncAttributeMaxDynamicSharedMemorySize, SMEM_BYTES);

    init_kernel<<<1, 32>>>();
    gate_ln_kernel<<<T, 256>>>(x, gw);
    offsets_kernel<<<1, 32>>>();
    scatter_kernel<<<(totalRows + 255) / 256, 256>>>(totalRows);

    dim3 g1(HD / TN, (totalRows + TM - 1) / TM, NE);
    gemm_mma<true><<<g1, NTH, SMEM_BYTES>>>(w1, b1, lns, lnb);

    dim3 g2(D / TN, (totalRows + TM - 1) / TM, NE);
    gemm_mma<false><<<g2, NTH, SMEM_BYTES>>>(w2, b2, nullptr, nullptr);

    combine_kernel<<<(T * (D / 4) + 255) / 256, 256>>>(out, T);
}

// round 6
// speedup vs baseline: 2.5367x; 1.7200x over previous
#include <cuda_runtime.h>
#include <cuda_bf16.h>
#include <math.h>
#include <stdint.h>

#define D     1024
#define HD    4096
#define NE    8
#define TOPK  2
#define MAXT  8192
#define MAXROWS (MAXT * TOPK)
#define LN_EPS 1e-5f

// GEMM tiling
#define TM 128
#define TN 128
#define KC 64                        // 64 bf16 = 128B = swizzle atom row
#define TB 16384                     // one 128x64 bf16 tile
#define BUFB (4 * TB)                // Ahi, Alo, Bhi, Blo per stage
#define NSTAGE 3
#define SMEM_BYTES (NSTAGE * BUFB)   // 196608
#define NTH 512

// ---------------- scratch ----------------------------------------------------
__device__ __nv_bfloat16 g_xnh[(size_t)MAXT * D];
__device__ __nv_bfloat16 g_xnl[(size_t)MAXT * D];
__device__ __nv_bfloat16 g_h1h[(size_t)MAXROWS * HD];
__device__ __nv_bfloat16 g_h1l[(size_t)MAXROWS * HD];
__device__ __nv_bfloat16 g_w1h[(size_t)NE * HD * D];   // [E][H][D] transposed
__device__ __nv_bfloat16 g_w1l[(size_t)NE * HD * D];
__device__ __nv_bfloat16 g_w2h[(size_t)NE * D * HD];   // [E][D][H] transposed
__device__ __nv_bfloat16 g_w2l[(size_t)NE * D * HD];
__device__ float g_b1f[(size_t)NE * HD];
__device__ float g_y [(size_t)MAXROWS * D];
__device__ float g_wts[MAXROWS];
__device__ int   g_sel[MAXROWS];
__device__ int   g_rowmap[MAXROWS];
__device__ int   g_counts[NE];
__device__ int   g_offsets[NE + 1];
__device__ int   g_cursor[NE];

// ---------------- helpers ----------------------------------------------------
__device__ __forceinline__ uint32_t smem_u32(const void* p) {
    uint32_t a;
    asm("{ .reg .u64 t; cvta.to.shared.u64 t, %1; cvt.u32.u64 %0, t; }"
        : "=r"(a) : "l"(p));
    return a;
}
// swizzle: row stride 128B, XOR (row&7)*16 into column bits
#define SWZC(row, col) ((uint32_t)((row) * 128 + ((col) ^ (((row) & 7) * 16))))

#define CPASYNC16(dst, src) \
    asm volatile("cp.async.cg.shared.global [%0], [%1], 16;" \
                 :: "r"(dst), "l"(src))
#define CP_COMMIT() asm volatile("cp.async.commit_group;")
#define CP_WAIT1()  asm volatile("cp.async.wait_group 1;")
#define CP_WAIT0()  asm volatile("cp.async.wait_group 0;")

#define LDM4(r0, r1, r2, r3, addr) \
    asm volatile("ldmatrix.sync.aligned.m8n8.x4.shared.b16 {%0,%1,%2,%3}, [%4];" \
        : "=r"(r0), "=r"(r1), "=r"(r2), "=r"(r3) : "r"(addr))

#define MMA16816(c, a, b) \
    asm volatile("mma.sync.aligned.m16n8k16.row.col.f32.bf16.bf16.f32 " \
        "{%0,%1,%2,%3}, {%4,%5,%6,%7}, {%8,%9}, {%0,%1,%2,%3};" \
        : "+f"((c)[0]), "+f"((c)[1]), "+f"((c)[2]), "+f"((c)[3]) \
        : "r"((a)[0]), "r"((a)[1]), "r"((a)[2]), "r"((a)[3]), \
          "r"((b)[0]), "r"((b)[1]))

__device__ __forceinline__ uint32_t pack_bf2(float a, float b) {
    __nv_bfloat162 h = __floats2bfloat162_rn(a, b);
    return *reinterpret_cast<uint32_t*>(&h);
}

// ---------------- weight transpose + split (+ optional scale fold) -----------
// W: [E][KD][NH] fp32 -> out hi/lo: [E][NH][KD] bf16 (k contiguous)
__global__ __launch_bounds__(1024) void convw_kernel(
    const float* __restrict__ W, const float* __restrict__ scale,
    __nv_bfloat16* __restrict__ oh, __nv_bfloat16* __restrict__ ol,
    int KD, int NH)
{
    __shared__ float tile[32][33];
    const int e = blockIdx.z;
    const int dr = blockIdx.x * 32 + threadIdx.y;
    const int hr = blockIdx.y * 32 + threadIdx.x;
    tile[threadIdx.y][threadIdx.x] = W[((size_t)e * KD + dr) * NH + hr];
    __syncthreads();
    const int hw = blockIdx.y * 32 + threadIdx.y;
    const int dw = blockIdx.x * 32 + threadIdx.x;
    float v = tile[threadIdx.x][threadIdx.y];
    if (scale) v *= scale[(size_t)e * KD + dw];
    const __nv_bfloat16 hb = __float2bfloat16_rn(v);
    const __nv_bfloat16 lb = __float2bfloat16_rn(v - __bfloat162float(hb));
    const size_t oi = ((size_t)e * NH + hw) * KD + dw;
    oh[oi] = hb; ol[oi] = lb;
}

// b1'[e][h] = b1[e][h] + sum_d ln_bias[e][d] * W1[e][d][h]   (deterministic)
__global__ __launch_bounds__(256) void foldb1_kernel(
    const float* __restrict__ w1, const float* __restrict__ b1,
    const float* __restrict__ lnb)
{
    const int e = blockIdx.y;
    const int h = blockIdx.x * 256 + threadIdx.x;
    float acc = 0.f;
    const float* wp = w1 + (size_t)e * D * HD + h;
    const float* bp = lnb + (size_t)e * D;
    for (int d = 0; d < D; d++) acc = fmaf(bp[d], wp[(size_t)d * HD], acc);
    g_b1f[(size_t)e * HD + h] = b1[(size_t)e * HD + h] + acc;
}

// ---------------- routing ----------------------------------------------------
__global__ void init_kernel() {
    if (threadIdx.x < NE) g_counts[threadIdx.x] = 0;
}

__global__ __launch_bounds__(256) void gate_ln_kernel(
    const float* __restrict__ x, const float* __restrict__ gw)
{
    const int t   = blockIdx.x;
    const int tid = threadIdx.x;
    __shared__ float sh_ws[8], sh_wq[8], sh_wl[8][8];
    __shared__ float sh_mu, sh_rstd;

    const float4 xv = reinterpret_cast<const float4*>(x + (size_t)t * D)[tid];
    float s = xv.x + xv.y + xv.z + xv.w;
    float q = xv.x * xv.x + xv.y * xv.y + xv.z * xv.z + xv.w * xv.w;

    float acc[8];
#pragma unroll
    for (int e = 0; e < 8; e++) acc[e] = 0.f;
    const float xs[4] = {xv.x, xv.y, xv.z, xv.w};
#pragma unroll
    for (int j = 0; j < 4; j++) {
        const int d = tid * 4 + j;
        const float4 g0 = *reinterpret_cast<const float4*>(gw + (size_t)d * 8);
        const float4 g1 = *reinterpret_cast<const float4*>(gw + (size_t)d * 8 + 4);
        const float xj = xs[j];
        acc[0] = fmaf(xj, g0.x, acc[0]); acc[1] = fmaf(xj, g0.y, acc[1]);
        acc[2] = fmaf(xj, g0.z, acc[2]); acc[3] = fmaf(xj, g0.w, acc[3]);
        acc[4] = fmaf(xj, g1.x, acc[4]); acc[5] = fmaf(xj, g1.y, acc[5]);
        acc[6] = fmaf(xj, g1.z, acc[6]); acc[7] = fmaf(xj, g1.w, acc[7]);
    }
#pragma unroll
    for (int o = 16; o > 0; o >>= 1) {
        s += __shfl_xor_sync(0xffffffffu, s, o);
        q += __shfl_xor_sync(0xffffffffu, q, o);
#pragma unroll
        for (int e = 0; e < 8; e++)
            acc[e] += __shfl_xor_sync(0xffffffffu, acc[e], o);
    }
    const int wid = tid >> 5, lane = tid & 31;
    if (lane == 0) {
        sh_ws[wid] = s; sh_wq[wid] = q;
#pragma unroll
        for (int e = 0; e < 8; e++) sh_wl[wid][e] = acc[e];
    }
    __syncthreads();

    if (tid == 0) {
        float S = 0.f, Q = 0.f, L[8];
#pragma unroll
        for (int e = 0; e < 8; e++) L[e] = 0.f;
        for (int w = 0; w < 8; w++) {
            S += sh_ws[w]; Q += sh_wq[w];
#pragma unroll
            for (int e = 0; e < 8; e++) L[e] += sh_wl[w][e];
        }
        const float mu = S * (1.f / (float)D);
        float var = Q * (1.f / (float)D) - mu * mu;
        if (var < 0.f) var = 0.f;
        sh_mu = mu; sh_rstd = rsqrtf(var + LN_EPS);

        float mx = L[0];
#pragma unroll
        for (int e = 1; e < 8; e++) mx = fmaxf(mx, L[e]);
        float p[8], se = 0.f;
#pragma unroll
        for (int e = 0; e < 8; e++) { p[e] = expf(L[e] - mx); se += p[e]; }
        const float inv = 1.f / se;
#pragma unroll
        for (int e = 0; e < 8; e++) p[e] *= inv;

        int i0 = 0; float p0 = p[0];
#pragma unroll
        for (int e = 1; e < 8; e++) if (p[e] > p0) { p0 = p[e]; i0 = e; }
        int i1 = -1; float p1 = -1e30f;
#pragma unroll
        for (int e = 0; e < 8; e++)
            if (e != i0 && p[e] > p1) { p1 = p[e]; i1 = e; }

        const float ew = expf(p1 - p0);
        g_sel[2 * t] = i0;  g_sel[2 * t + 1] = i1;
        g_wts[2 * t] = 1.f / (1.f + ew);
        g_wts[2 * t + 1] = ew / (1.f + ew);
        atomicAdd(&g_counts[i0], 1);
        atomicAdd(&g_counts[i1], 1);
    }
    __syncthreads();

    const float mu = sh_mu, rstd = sh_rstd;
    float v[4];
    v[0] = (xv.x - mu) * rstd; v[1] = (xv.y - mu) * rstd;
    v[2] = (xv.z - mu) * rstd; v[3] = (xv.w - mu) * rstd;
    float h[4], l[4];
#pragma unroll
    for (int j = 0; j < 4; j++) {
        __nv_bfloat16 hb = __float2bfloat16_rn(v[j]);
        h[j] = __bfloat162float(hb);
        l[j] = v[j] - h[j];
    }
    uint32_t* oh = reinterpret_cast<uint32_t*>(g_xnh + (size_t)t * D);
    uint32_t* ol = reinterpret_cast<uint32_t*>(g_xnl + (size_t)t * D);
    oh[tid * 2]     = pack_bf2(h[0], h[1]);
    oh[tid * 2 + 1] = pack_bf2(h[2], h[3]);
    ol[tid * 2]     = pack_bf2(l[0], l[1]);
    ol[tid * 2 + 1] = pack_bf2(l[2], l[3]);
}

__global__ void offsets_kernel() {
    if (threadIdx.x == 0) {
        int o = 0;
        for (int e = 0; e < NE; e++) {
            g_offsets[e] = o; g_cursor[e] = o; o += g_counts[e];
        }
        g_offsets[NE] = o;
    }
}

__global__ void scatter_kernel(int total) {
    const int i = blockIdx.x * blockDim.x + threadIdx.x;
    if (i < total) {
        const int e = g_sel[i];
        const int pos = atomicAdd(&g_cursor[e], 1);
        g_rowmap[pos] = i;
    }
}

// ---------------- cp.async pipelined mma.sync grouped GEMM -------------------
// G1: h1[row,:] = gelu(xn[tok] @ (s·W1[e]) + b1'[e])   KTOT=D,  NTOT=HD
// G2: y[slot,:] = wts[slot] * (h1[row,:] @ W2[e] + b2[e])
template<bool G1>
__global__ __launch_bounds__(NTH, 1) void gemm_cp(
    const float* __restrict__ bias)
{
    constexpr int KTOT = G1 ? D : HD;
    constexpr int NTOT = G1 ? HD : D;
    constexpr int NC   = KTOT / KC;

    const int e    = blockIdx.z;
    const int seg0 = g_offsets[e];
    const int nseg = g_offsets[e + 1] - seg0;
    const int m0   = blockIdx.y * TM;
    if (m0 >= nseg) return;
    const int n0   = blockIdx.x * TN;

    extern __shared__ __align__(1024) char smem[];
    const uint32_t sb = smem_u32(smem);
    const int tid = threadIdx.x;

    // ---- per-thread copy source pointers (row = tid>>2, 2x16B at (tid&3)*32B)
    const int crow = tid >> 2;          // 0..127
    const int ck   = (tid & 3) * 16;    // element offset of first 16 bf16
    const bool cval = (m0 + crow) < nseg;
    int arow;
    if (G1) arow = cval ? (g_rowmap[seg0 + m0 + crow] >> 1) : 0;
    else    arow = cval ? (seg0 + m0 + crow) : 0;
    const __nv_bfloat16* srcAh =
        (G1 ? g_xnh + (size_t)arow * D : g_h1h + (size_t)arow * HD) + ck;
    const __nv_bfloat16* srcAl =
        (G1 ? g_xnl + (size_t)arow * D : g_h1l + (size_t)arow * HD) + ck;
    const __nv_bfloat16* srcBh =
        (G1 ? g_w1h : g_w2h) + ((size_t)e * NTOT + n0 + crow) * KTOT + ck;
    const __nv_bfloat16* srcBl =
        (G1 ? g_w1l : g_w2l) + ((size_t)e * NTOT + n0 + crow) * KTOT + ck;

    const uint32_t dst0 = SWZC(crow, (tid & 3) * 32);
    const uint32_t dst1 = SWZC(crow, (tid & 3) * 32 + 16);

    auto issue = [&](int stage, int c) {
        const uint32_t base = sb + stage * BUFB;
        const int kb = c * KC;
        CPASYNC16(base + 0 * TB + dst0, srcAh + kb);
        CPASYNC16(base + 0 * TB + dst1, srcAh + kb + 8);
        CPASYNC16(base + 1 * TB + dst0, srcAl + kb);
        CPASYNC16(base + 1 * TB + dst1, srcAl + kb + 8);
        CPASYNC16(base + 2 * TB + dst0, srcBh + kb);
        CPASYNC16(base + 2 * TB + dst1, srcBh + kb + 8);
        CPASYNC16(base + 3 * TB + dst0, srcBl + kb);
        CPASYNC16(base + 3 * TB + dst1, srcBl + kb + 8);
        CP_COMMIT();
    };

    // ---- consumer state: 16 warps, 32x32 warp tiles ----
    const int wid    = tid >> 5;
    const int lane   = tid & 31;
    const int warp_m = wid & 3;
    const int warp_n = wid >> 2;

    float acc[2][4][4];
#pragma unroll
    for (int i = 0; i < 2; i++)
#pragma unroll
        for (int j = 0; j < 4; j++)
#pragma unroll
            for (int k = 0; k < 4; k++) acc[i][j][k] = 0.f;

    const uint32_t sel    = (uint32_t)((lane & 7) << 4);
    const uint32_t rowAb  = (uint32_t)((warp_m * 32 + ((lane >> 3) & 1) * 8 + (lane & 7)) * 128);
    const uint32_t colA16 = (uint32_t)((lane >> 4) * 16);
    const uint32_t rowBb  = (uint32_t)((warp_n * 32 + (lane >> 4) * 8 + (lane & 7)) * 128);
    const uint32_t colB16 = (uint32_t)(((lane >> 3) & 1) * 16);

    auto compute = [&](int stage) {
        const uint32_t aH = sb + stage * BUFB;
        const uint32_t aL = aH + TB;
        const uint32_t bH = aH + 2 * TB;
        const uint32_t bL = aH + 3 * TB;
#pragma unroll
        for (int ks = 0; ks < 4; ks++) {
            const uint32_t colA = ((uint32_t)(ks * 32) + colA16) ^ sel;
            const uint32_t colB = ((uint32_t)(ks * 32) + colB16) ^ sel;
            uint32_t ah[2][4], al[2][4], bh[4][2], bl[4][2];
#pragma unroll
            for (int i = 0; i < 2; i++)
                LDM4(ah[i][0], ah[i][1], ah[i][2], ah[i][3],
                     aH + rowAb + (uint32_t)(i * 16 * 128) + colA);
#pragma unroll
            for (int j2 = 0; j2 < 2; j2++) {
                uint32_t t0, t1, t2, t3;
                LDM4(t0, t1, t2, t3, bH + rowBb + (uint32_t)(j2 * 16 * 128) + colB);
                bh[2*j2][0]=t0; bh[2*j2][1]=t1; bh[2*j2+1][0]=t2; bh[2*j2+1][1]=t3;
            }
#pragma unroll
            for (int i = 0; i < 2; i++)
#pragma unroll
                for (int j = 0; j < 4; j++) MMA16816(acc[i][j], ah[i], bh[j]);
#pragma unroll
            for (int j2 = 0; j2 < 2; j2++) {
                uint32_t t0, t1, t2, t3;
                LDM4(t0, t1, t2, t3, bL + rowBb + (uint32_t)(j2 * 16 * 128) + colB);
                bl[2*j2][0]=t0; bl[2*j2][1]=t1; bl[2*j2+1][0]=t2; bl[2*j2+1][1]=t3;
            }
#pragma unroll
            for (int i = 0; i < 2; i++)
#pragma unroll
                for (int j = 0; j < 4; j++) MMA16816(acc[i][j], ah[i], bl[j]);
#pragma unroll
            for (int i = 0; i < 2; i++)
                LDM4(al[i][0], al[i][1], al[i][2], al[i][3],
                     aL + rowAb + (uint32_t)(i * 16 * 128) + colA);
#pragma unroll
            for (int i = 0; i < 2; i++)
#pragma unroll
                for (int j = 0; j < 4; j++) MMA16816(acc[i][j], al[i], bh[j]);
        }
    };

    // ---- pipeline: 3 stages ----
    issue(0, 0);
    issue(1, 1);
    int stage = 0;
    for (int c = 0; c < NC; c++) {
        if (c + 1 < NC) { CP_WAIT1(); } else { CP_WAIT0(); }
        __syncthreads();
        if (c + 2 < NC) {
            int s2 = stage + 2; if (s2 >= NSTAGE) s2 -= NSTAGE;
            issue(s2, c + 2);
        }
        compute(stage);
        __syncthreads();
        if (++stage == NSTAGE) stage = 0;
    }

    // ---- epilogue ----
    {
        const int r4 = lane >> 2;
        const int c2 = 2 * (lane & 3);
        const int nb = n0 + warp_n * 32;
        const float* bp = G1 ? (g_b1f + (size_t)e * NTOT) : (bias + (size_t)e * NTOT);
        float2 bb[4];
#pragma unroll
        for (int j = 0; j < 4; j++)
            bb[j] = *reinterpret_cast<const float2*>(bp + nb + j * 8 + c2);
#pragma unroll
        for (int i = 0; i < 2; i++) {
#pragma unroll
            for (int h = 0; h < 2; h++) {
                const int mloc = warp_m * 32 + i * 16 + h * 8 + r4;
                if (m0 + mloc >= nseg) continue;
                if (G1) {
                    const size_t rb = (size_t)(seg0 + m0 + mloc) * HD + nb;
#pragma unroll
                    for (int j = 0; j < 4; j++) {
                        float y0 = acc[i][j][2*h]   + bb[j].x;
                        float y1 = acc[i][j][2*h+1] + bb[j].y;
                        y0 = 0.5f * y0 * (1.f + erff(y0 * 0.70710678118654752f));
                        y1 = 0.5f * y1 * (1.f + erff(y1 * 0.70710678118654752f));
                        const __nv_bfloat16 h0 = __float2bfloat16_rn(y0);
                        const __nv_bfloat16 h1 = __float2bfloat16_rn(y1);
                        const float l0 = y0 - __bfloat162float(h0);
                        const float l1 = y1 - __bfloat162float(h1);
                        const size_t o2 = (rb + j * 8 + c2) >> 1;
                        reinterpret_cast<uint32_t*>(g_h1h)[o2] =
                            pack_bf2(__bfloat162float(h0), __bfloat162float(h1));
                        reinterpret_cast<uint32_t*>(g_h1l)[o2] = pack_bf2(l0, l1);
                    }
                } else {
                    const int slot = g_rowmap[seg0 + m0 + mloc];
                    const float wt = g_wts[slot];
                    float* op = g_y + (size_t)slot * D + nb;
#pragma unroll
                    for (int j = 0; j < 4; j++) {
                        const float y0 = (acc[i][j][2*h]   + bb[j].x) * wt;
                        const float y1 = (acc[i][j][2*h+1] + bb[j].y) * wt;
                        *reinterpret_cast<float2*>(op + j * 8 + c2) = make_float2(y0, y1);
                    }
                }
            }
        }
    }
}

// ---------------- combine ----------------------------------------------------
__global__ void combine_kernel(float* __restrict__ out, int T) {
    const int nd4 = D / 4;
    const int i = blockIdx.x * blockDim.x + threadIdx.x;
    if (i >= T * nd4) return;
    const int t = i / nd4, d4 = i % nd4;
    const float4* y4 = reinterpret_cast<const float4*>(g_y);
    const float4 a = y4[(size_t)(2 * t) * nd4 + d4];
    const float4 b = y4[(size_t)(2 * t + 1) * nd4 + d4];
    reinterpret_cast<float4*>(out)[i] =
        make_float4(a.x + b.x, a.y + b.y, a.z + b.z, a.w + b.w);
}

// ---------------- launch -----------------------------------------------------
extern "C" void kernel_launch(void* const* d_in, const int* in_sizes, int n_in,
                              void* d_out, int out_size)
{
    const float* x   = (const float*)d_in[0];
    const float* gw  = (const float*)d_in[1];
    const float* lns = (const float*)d_in[2];
    const float* lnb = (const float*)d_in[3];
    const float* w1  = (const float*)d_in[4];
    const float* b1  = (const float*)d_in[5];
    const float* w2  = (const float*)d_in[6];
    const float* b2  = (const float*)d_in[7];
    float* out = (float*)d_out;

    const int T = in_sizes[0] / D;
    const int totalRows = T * TOPK;

    cudaFuncSetAttribute(gemm_cp<true>,
                         cudaFuncAttributeMaxDynamicSharedMemorySize, SMEM_BYTES);
    cudaFuncSetAttribute(gemm_cp<false>,
                         cudaFuncAttributeMaxDynamicSharedMemorySize, SMEM_BYTES);

    // weight prep (independent of routing)
    __nv_bfloat16 *w1h, *w1l, *w2h, *w2l;
    cudaGetSymbolAddress((void**)&w1h, g_w1h);
    cudaGetSymbolAddress((void**)&w1l, g_w1l);
    cudaGetSymbolAddress((void**)&w2h, g_w2h);
    cudaGetSymbolAddress((void**)&w2l, g_w2l);

    dim3 blk32(32, 32);
    convw_kernel<<<dim3(D / 32, HD / 32, NE), blk32>>>(w1, lns, w1h, w1l, D, HD);
    convw_kernel<<<dim3(HD / 32, D / 32, NE), blk32>>>(w2, nullptr, w2h, w2l, HD, D);
    foldb1_kernel<<<dim3(HD / 256, NE), 256>>>(w1, b1, lnb);

    init_kernel<<<1, 32>>>();
    gate_ln_kernel<<<T, 256>>>(x, gw);
    offsets_kernel<<<1, 32>>>();
    scatter_kernel<<<(totalRows + 255) / 256, 256>>>(totalRows);

    dim3 g1(HD / TN, (totalRows + TM - 1) / TM, NE);
    gemm_cp<true><<<g1, NTH, SMEM_BYTES>>>(nullptr);

    dim3 g2(D / TN, (totalRows + TM - 1) / TM, NE);
    gemm_cp<false><<<g2, NTH, SMEM_BYTES>>>(b2);

    combine_kernel<<<(T * (D / 4) + 255) / 256, 256>>>(out, T);
}

// round 7
// speedup vs baseline: 3.1755x; 1.2518x over previous
#include <cuda_runtime.h>
#include <cuda_fp16.h>
#include <math.h>
#include <stdint.h>

#define D     1024
#define HD    4096
#define NE    8
#define TOPK  2
#define MAXT  8192
#define MAXROWS (MAXT * TOPK)
#define LN_EPS 1e-5f

// GEMM tiling
#define TM 128
#define TN 128
#define KC 64                        // 64 fp16 = 128B = swizzle atom row
#define TB 16384                     // one 128x64 fp16 tile
#define BUFB (3 * TB)                // A, Bhi, Blo per stage
#define NSTAGE 4
#define SMEM_BYTES (NSTAGE * BUFB)   // 196608
#define NTH 512

// ---------------- scratch ----------------------------------------------------
__device__ __half g_xn [(size_t)MAXT * D];
__device__ __half g_h1 [(size_t)MAXROWS * HD];
__device__ __half g_w1h[(size_t)NE * HD * D];   // [E][H][D] transposed
__device__ __half g_w1l[(size_t)NE * HD * D];
__device__ __half g_w2h[(size_t)NE * D * HD];   // [E][D][H] transposed
__device__ __half g_w2l[(size_t)NE * D * HD];
__device__ float g_b1f[(size_t)NE * HD];
__device__ float g_y [(size_t)MAXROWS * D];
__device__ float g_wts[MAXROWS];
__device__ int   g_sel[MAXROWS];
__device__ int   g_rowmap[MAXROWS];
__device__ int   g_counts[NE];
__device__ int   g_offsets[NE + 1];
__device__ int   g_cursor[NE];

// ---------------- helpers ----------------------------------------------------
__device__ __forceinline__ uint32_t smem_u32(const void* p) {
    uint32_t a;
    asm("{ .reg .u64 t; cvta.to.shared.u64 t, %1; cvt.u32.u64 %0, t; }"
        : "=r"(a) : "l"(p));
    return a;
}
// swizzle: row stride 128B, XOR (row&7)*16 into column bits
#define SWZC(row, col) ((uint32_t)((row) * 128 + ((col) ^ (((row) & 7) * 16))))

#define CPASYNC16(dst, src) \
    asm volatile("cp.async.cg.shared.global [%0], [%1], 16;" \
                 :: "r"(dst), "l"(src))
#define CP_COMMIT() asm volatile("cp.async.commit_group;")
#define CP_WAIT2()  asm volatile("cp.async.wait_group 2;")
#define CP_WAIT1()  asm volatile("cp.async.wait_group 1;")
#define CP_WAIT0()  asm volatile("cp.async.wait_group 0;")

#define LDM4(r0, r1, r2, r3, addr) \
    asm volatile("ldmatrix.sync.aligned.m8n8.x4.shared.b16 {%0,%1,%2,%3}, [%4];" \
        : "=r"(r0), "=r"(r1), "=r"(r2), "=r"(r3) : "r"(addr))

#define MMA16816(c, a, b) \
    asm volatile("mma.sync.aligned.m16n8k16.row.col.f32.f16.f16.f32 " \
        "{%0,%1,%2,%3}, {%4,%5,%6,%7}, {%8,%9}, {%0,%1,%2,%3};" \
        : "+f"((c)[0]), "+f"((c)[1]), "+f"((c)[2]), "+f"((c)[3]) \
        : "r"((a)[0]), "r"((a)[1]), "r"((a)[2]), "r"((a)[3]), \
          "r"((b)[0]), "r"((b)[1]))

__device__ __forceinline__ uint32_t pack_h2(float a, float b) {
    __half2 h = __floats2half2_rn(a, b);
    return *reinterpret_cast<uint32_t*>(&h);
}

// ---------------- weight transpose + split (+ optional scale fold) -----------
// W: [E][KD][NH] fp32 -> hi/lo fp16: [E][NH][KD] (k contiguous)
__global__ __launch_bounds__(1024) void convw_kernel(
    const float* __restrict__ W, const float* __restrict__ scale,
    __half* __restrict__ oh, __half* __restrict__ ol,
    int KD, int NH)
{
    __shared__ float tile[32][33];
    const int e = blockIdx.z;
    const int dr = blockIdx.x * 32 + threadIdx.y;
    const int hr = blockIdx.y * 32 + threadIdx.x;
    tile[threadIdx.y][threadIdx.x] = W[((size_t)e * KD + dr) * NH + hr];
    __syncthreads();
    const int hw = blockIdx.y * 32 + threadIdx.y;
    const int dw = blockIdx.x * 32 + threadIdx.x;
    float v = tile[threadIdx.x][threadIdx.y];
    if (scale) v *= scale[(size_t)e * KD + dw];
    const __half hb = __float2half_rn(v);
    const __half lb = __float2half_rn(v - __half2float(hb));
    const size_t oi = ((size_t)e * NH + hw) * KD + dw;
    oh[oi] = hb; ol[oi] = lb;
}

// b1'[e][h] = b1[e][h] + sum_d ln_bias[e][d] * W1[e][d][h]   (deterministic)
__global__ __launch_bounds__(256) void foldb1_kernel(
    const float* __restrict__ w1, const float* __restrict__ b1,
    const float* __restrict__ lnb)
{
    const int e = blockIdx.y;
    const int h = blockIdx.x * 256 + threadIdx.x;
    float acc = 0.f;
    const float* wp = w1 + (size_t)e * D * HD + h;
    const float* bp = lnb + (size_t)e * D;
    for (int d = 0; d < D; d++) acc = fmaf(bp[d], wp[(size_t)d * HD], acc);
    g_b1f[(size_t)e * HD + h] = b1[(size_t)e * HD + h] + acc;
}

// ---------------- routing ----------------------------------------------------
__global__ void init_kernel() {
    if (threadIdx.x < NE) g_counts[threadIdx.x] = 0;
}

__global__ __launch_bounds__(256) void gate_ln_kernel(
    const float* __restrict__ x, const float* __restrict__ gw)
{
    const int t   = blockIdx.x;
    const int tid = threadIdx.x;
    __shared__ float sh_ws[8], sh_wq[8], sh_wl[8][8];
    __shared__ float sh_mu, sh_rstd;

    const float4 xv = reinterpret_cast<const float4*>(x + (size_t)t * D)[tid];
    float s = xv.x + xv.y + xv.z + xv.w;
    float q = xv.x * xv.x + xv.y * xv.y + xv.z * xv.z + xv.w * xv.w;

    float acc[8];
#pragma unroll
    for (int e = 0; e < 8; e++) acc[e] = 0.f;
    const float xs[4] = {xv.x, xv.y, xv.z, xv.w};
#pragma unroll
    for (int j = 0; j < 4; j++) {
        const int d = tid * 4 + j;
        const float4 g0 = *reinterpret_cast<const float4*>(gw + (size_t)d * 8);
        const float4 g1 = *reinterpret_cast<const float4*>(gw + (size_t)d * 8 + 4);
        const float xj = xs[j];
        acc[0] = fmaf(xj, g0.x, acc[0]); acc[1] = fmaf(xj, g0.y, acc[1]);
        acc[2] = fmaf(xj, g0.z, acc[2]); acc[3] = fmaf(xj, g0.w, acc[3]);
        acc[4] = fmaf(xj, g1.x, acc[4]); acc[5] = fmaf(xj, g1.y, acc[5]);
        acc[6] = fmaf(xj, g1.z, acc[6]); acc[7] = fmaf(xj, g1.w, acc[7]);
    }
#pragma unroll
    for (int o = 16; o > 0; o >>= 1) {
        s += __shfl_xor_sync(0xffffffffu, s, o);
        q += __shfl_xor_sync(0xffffffffu, q, o);
#pragma unroll
        for (int e = 0; e < 8; e++)
            acc[e] += __shfl_xor_sync(0xffffffffu, acc[e], o);
    }
    const int wid = tid >> 5, lane = tid & 31;
    if (lane == 0) {
        sh_ws[wid] = s; sh_wq[wid] = q;
#pragma unroll
        for (int e = 0; e < 8; e++) sh_wl[wid][e] = acc[e];
    }
    __syncthreads();

    if (tid == 0) {
        float S = 0.f, Q = 0.f, L[8];
#pragma unroll
        for (int e = 0; e < 8; e++) L[e] = 0.f;
        for (int w = 0; w < 8; w++) {
            S += sh_ws[w]; Q += sh_wq[w];
#pragma unroll
            for (int e = 0; e < 8; e++) L[e] += sh_wl[w][e];
        }
        const float mu = S * (1.f / (float)D);
        float var = Q * (1.f / (float)D) - mu * mu;
        if (var < 0.f) var = 0.f;
        sh_mu = mu; sh_rstd = rsqrtf(var + LN_EPS);

        float mx = L[0];
#pragma unroll
        for (int e = 1; e < 8; e++) mx = fmaxf(mx, L[e]);
        float p[8], se = 0.f;
#pragma unroll
        for (int e = 0; e < 8; e++) { p[e] = expf(L[e] - mx); se += p[e]; }
        const float inv = 1.f / se;
#pragma unroll
        for (int e = 0; e < 8; e++) p[e] *= inv;

        int i0 = 0; float p0 = p[0];
#pragma unroll
        for (int e = 1; e < 8; e++) if (p[e] > p0) { p0 = p[e]; i0 = e; }
        int i1 = -1; float p1 = -1e30f;
#pragma unroll
        for (int e = 0; e < 8; e++)
            if (e != i0 && p[e] > p1) { p1 = p[e]; i1 = e; }

        const float ew = expf(p1 - p0);
        g_sel[2 * t] = i0;  g_sel[2 * t + 1] = i1;
        g_wts[2 * t] = 1.f / (1.f + ew);
        g_wts[2 * t + 1] = ew / (1.f + ew);
        atomicAdd(&g_counts[i0], 1);
        atomicAdd(&g_counts[i1], 1);
    }
    __syncthreads();

    const float mu = sh_mu, rstd = sh_rstd;
    uint32_t* o = reinterpret_cast<uint32_t*>(g_xn + (size_t)t * D);
    o[tid * 2]     = pack_h2((xv.x - mu) * rstd, (xv.y - mu) * rstd);
    o[tid * 2 + 1] = pack_h2((xv.z - mu) * rstd, (xv.w - mu) * rstd);
}

__global__ void offsets_kernel() {
    if (threadIdx.x == 0) {
        int o = 0;
        for (int e = 0; e < NE; e++) {
            g_offsets[e] = o; g_cursor[e] = o; o += g_counts[e];
        }
        g_offsets[NE] = o;
    }
}

__global__ void scatter_kernel(int total) {
    const int i = blockIdx.x * blockDim.x + threadIdx.x;
    if (i < total) {
        const int e = g_sel[i];
        const int pos = atomicAdd(&g_cursor[e], 1);
        g_rowmap[pos] = i;
    }
}

// ---------------- cp.async pipelined mma.sync grouped GEMM -------------------
// fp16: A single plane, B hi+lo planes; C = A@Bh + A@Bl
// G1: h1[row,:] = gelu(xn[tok] @ (s·W1[e]) + b1'[e])   KTOT=D,  NTOT=HD
// G2: y[slot,:] = wts[slot] * (h1[row,:] @ W2[e] + b2[e])
template<bool G1>
__global__ __launch_bounds__(NTH, 1) void gemm_cp(
    const float* __restrict__ bias)
{
    constexpr int KTOT = G1 ? D : HD;
    constexpr int NTOT = G1 ? HD : D;
    constexpr int NC   = KTOT / KC;

    const int e    = blockIdx.z;
    const int seg0 = g_offsets[e];
    const int nseg = g_offsets[e + 1] - seg0;
    const int m0   = blockIdx.y * TM;
    if (m0 >= nseg) return;
    const int n0   = blockIdx.x * TN;

    extern __shared__ __align__(1024) char smem[];
    const uint32_t sb = smem_u32(smem);
    const int tid = threadIdx.x;

    // copy mapping: row = tid>>2, 2x16B at byte (tid&3)*32
    const int crow = tid >> 2;
    const int ck   = (tid & 3) * 16;
    const bool cval = (m0 + crow) < nseg;
    int arow;
    if (G1) arow = cval ? (g_rowmap[seg0 + m0 + crow] >> 1) : 0;
    else    arow = cval ? (seg0 + m0 + crow) : 0;
    const __half* srcA =
        (G1 ? g_xn + (size_t)arow * D : g_h1 + (size_t)arow * HD) + ck;
    const __half* srcBh =
        (G1 ? g_w1h : g_w2h) + ((size_t)e * NTOT + n0 + crow) * KTOT + ck;
    const __half* srcBl =
        (G1 ? g_w1l : g_w2l) + ((size_t)e * NTOT + n0 + crow) * KTOT + ck;

    const uint32_t dst0 = SWZC(crow, (tid & 3) * 32);
    const uint32_t dst1 = SWZC(crow, (tid & 3) * 32 + 16);

    auto issue = [&](int stage, int c) {
        const uint32_t base = sb + stage * BUFB;
        const int kb = c * KC;
        CPASYNC16(base + 0 * TB + dst0, srcA  + kb);
        CPASYNC16(base + 0 * TB + dst1, srcA  + kb + 8);
        CPASYNC16(base + 1 * TB + dst0, srcBh + kb);
        CPASYNC16(base + 1 * TB + dst1, srcBh + kb + 8);
        CPASYNC16(base + 2 * TB + dst0, srcBl + kb);
        CPASYNC16(base + 2 * TB + dst1, srcBl + kb + 8);
        CP_COMMIT();
    };

    // consumer: 16 warps, 32x32 warp tiles
    const int wid    = tid >> 5;
    const int lane   = tid & 31;
    const int warp_m = wid & 3;
    const int warp_n = wid >> 2;

    float acc[2][4][4];
#pragma unroll
    for (int i = 0; i < 2; i++)
#pragma unroll
        for (int j = 0; j < 4; j++)
#pragma unroll
            for (int k = 0; k < 4; k++) acc[i][j][k] = 0.f;

    const uint32_t sel    = (uint32_t)((lane & 7) << 4);
    const uint32_t rowAb  = (uint32_t)((warp_m * 32 + ((lane >> 3) & 1) * 8 + (lane & 7)) * 128);
    const uint32_t colA16 = (uint32_t)((lane >> 4) * 16);
    const uint32_t rowBb  = (uint32_t)((warp_n * 32 + (lane >> 4) * 8 + (lane & 7)) * 128);
    const uint32_t colB16 = (uint32_t)(((lane >> 3) & 1) * 16);

    auto compute = [&](int stage) {
        const uint32_t aB = sb + stage * BUFB;
        const uint32_t bH = aB + TB;
        const uint32_t bL = aB + 2 * TB;
#pragma unroll
        for (int ks = 0; ks < 4; ks++) {
            const uint32_t colA = ((uint32_t)(ks * 32) + colA16) ^ sel;
            const uint32_t colB = ((uint32_t)(ks * 32) + colB16) ^ sel;
            uint32_t ah[2][4], bh[4][2], bl[4][2];
#pragma unroll
            for (int i = 0; i < 2; i++)
                LDM4(ah[i][0], ah[i][1], ah[i][2], ah[i][3],
                     aB + rowAb + (uint32_t)(i * 16 * 128) + colA);
#pragma unroll
            for (int j2 = 0; j2 < 2; j2++) {
                uint32_t t0, t1, t2, t3;
                LDM4(t0, t1, t2, t3, bH + rowBb + (uint32_t)(j2 * 16 * 128) + colB);
                bh[2*j2][0]=t0; bh[2*j2][1]=t1; bh[2*j2+1][0]=t2; bh[2*j2+1][1]=t3;
            }
#pragma unroll
            for (int i = 0; i < 2; i++)
#pragma unroll
                for (int j = 0; j < 4; j++) MMA16816(acc[i][j], ah[i], bh[j]);
#pragma unroll
            for (int j2 = 0; j2 < 2; j2++) {
                uint32_t t0, t1, t2, t3;
                LDM4(t0, t1, t2, t3, bL + rowBb + (uint32_t)(j2 * 16 * 128) + colB);
                bl[2*j2][0]=t0; bl[2*j2][1]=t1; bl[2*j2+1][0]=t2; bl[2*j2+1][1]=t3;
            }
#pragma unroll
            for (int i = 0; i < 2; i++)
#pragma unroll
                for (int j = 0; j < 4; j++) MMA16816(acc[i][j], ah[i], bl[j]);
        }
    };

    // pipeline: 4 stages, 3 in flight
    issue(0, 0);
    issue(1, 1);
    issue(2, 2);
    int stage = 0;
    for (int c = 0; c < NC; c++) {
        if (c + 2 < NC)      { CP_WAIT2(); }
        else if (c + 1 < NC) { CP_WAIT1(); }
        else                 { CP_WAIT0(); }
        __syncthreads();
        if (c + 3 < NC) issue((stage + 3) & 3, c + 3);
        compute(stage);
        __syncthreads();
        stage = (stage + 1) & 3;
    }

    // epilogue
    {
        const int r4 = lane >> 2;
        const int c2 = 2 * (lane & 3);
        const int nb = n0 + warp_n * 32;
        const float* bp = G1 ? (g_b1f + (size_t)e * NTOT) : (bias + (size_t)e * NTOT);
        float2 bb[4];
#pragma unroll
        for (int j = 0; j < 4; j++)
            bb[j] = *reinterpret_cast<const float2*>(bp + nb + j * 8 + c2);
#pragma unroll
        for (int i = 0; i < 2; i++) {
#pragma unroll
            for (int h = 0; h < 2; h++) {
                const int mloc = warp_m * 32 + i * 16 + h * 8 + r4;
                if (m0 + mloc >= nseg) continue;
                if (G1) {
                    const size_t rb = (size_t)(seg0 + m0 + mloc) * HD + nb;
#pragma unroll
                    for (int j = 0; j < 4; j++) {
                        float y0 = acc[i][j][2*h]   + bb[j].x;
                        float y1 = acc[i][j][2*h+1] + bb[j].y;
                        y0 = 0.5f * y0 * (1.f + erff(y0 * 0.70710678118654752f));
                        y1 = 0.5f * y1 * (1.f + erff(y1 * 0.70710678118654752f));
                        reinterpret_cast<uint32_t*>(g_h1)[(rb + j * 8 + c2) >> 1] =
                            pack_h2(y0, y1);
                    }
                } else {
                    const int slot = g_rowmap[seg0 + m0 + mloc];
                    const float wt = g_wts[slot];
                    float* op = g_y + (size_t)slot * D + nb;
#pragma unroll
                    for (int j = 0; j < 4; j++) {
                        const float y0 = (acc[i][j][2*h]   + bb[j].x) * wt;
                        const float y1 = (acc[i][j][2*h+1] + bb[j].y) * wt;
                        *reinterpret_cast<float2*>(op + j * 8 + c2) = make_float2(y0, y1);
                    }
                }
            }
        }
    }
}

// ---------------- combine ----------------------------------------------------
__global__ void combine_kernel(float* __restrict__ out, int T) {
    const int nd4 = D / 4;
    const int i = blockIdx.x * blockDim.x + threadIdx.x;
    if (i >= T * nd4) return;
    const int t = i / nd4, d4 = i % nd4;
    const float4* y4 = reinterpret_cast<const float4*>(g_y);
    const float4 a = y4[(size_t)(2 * t) * nd4 + d4];
    const float4 b = y4[(size_t)(2 * t + 1) * nd4 + d4];
    reinterpret_cast<float4*>(out)[i] =
        make_float4(a.x + b.x, a.y + b.y, a.z + b.z, a.w + b.w);
}

// ---------------- launch -----------------------------------------------------
extern "C" void kernel_launch(void* const* d_in, const int* in_sizes, int n_in,
                              void* d_out, int out_size)
{
    const float* x   = (const float*)d_in[0];
    const float* gw  = (const float*)d_in[1];
    const float* lns = (const float*)d_in[2];
    const float* lnb = (const float*)d_in[3];
    const float* w1  = (const float*)d_in[4];
    const float* b1  = (const float*)d_in[5];
    const float* w2  = (const float*)d_in[6];
    const float* b2  = (const float*)d_in[7];
    float* out = (float*)d_out;

    const int T = in_sizes[0] / D;
    const int totalRows = T * TOPK;

    cudaFuncSetAttribute(gemm_cp<true>,
                         cudaFuncAttributeMaxDynamicSharedMemorySize, SMEM_BYTES);
    cudaFuncSetAttribute(gemm_cp<false>,
                         cudaFuncAttributeMaxDynamicSharedMemorySize, SMEM_BYTES);

    __half *w1h, *w1l, *w2h, *w2l;
    cudaGetSymbolAddress((void**)&w1h, g_w1h);
    cudaGetSymbolAddress((void**)&w1l, g_w1l);
    cudaGetSymbolAddress((void**)&w2h, g_w2h);
    cudaGetSymbolAddress((void**)&w2l, g_w2l);

    dim3 blk32(32, 32);
    convw_kernel<<<dim3(D / 32, HD / 32, NE), blk32>>>(w1, lns, w1h, w1l, D, HD);
    convw_kernel<<<dim3(HD / 32, D / 32, NE), blk32>>>(w2, nullptr, w2h, w2l, HD, D);
    foldb1_kernel<<<dim3(HD / 256, NE), 256>>>(w1, b1, lnb);

    init_kernel<<<1, 32>>>();
    gate_ln_kernel<<<T, 256>>>(x, gw);
    offsets_kernel<<<1, 32>>>();
    scatter_kernel<<<(totalRows + 255) / 256, 256>>>(totalRows);

    dim3 g1(HD / TN, (totalRows + TM - 1) / TM, NE);
    gemm_cp<true><<<g1, NTH, SMEM_BYTES>>>(nullptr);

    dim3 g2(D / TN, (totalRows + TM - 1) / TM, NE);
    gemm_cp<false><<<g2, NTH, SMEM_BYTES>>>(b2);

    combine_kernel<<<(T * (D / 4) + 255) / 256, 256>>>(out, T);
}

// round 12
// speedup vs baseline: 4.5310x; 1.4269x over previous
#include <cuda_runtime.h>
#include <cuda_fp16.h>
#include <math.h>
#include <stdint.h>

#define D     1024
#define HD    4096
#define NE    8
#define TOPK  2
#define MAXT  8192
#define MAXROWS (MAXT * TOPK)
#define LN_EPS 1e-5f

// GEMM tiling
#define TM 128
#define TN 128
#define KC 64                        // 64 fp16 = 128B = swizzle atom row
#define TB 16384                     // one 128x64 fp16 tile
#define BUFB (2 * TB)                // A, B per stage
#define NSTAGE 6
#define SMEM_BYTES (NSTAGE * BUFB)   // 196608
#define NTH 512

// ---------------- scratch ----------------------------------------------------
__device__ __half g_xn [(size_t)MAXT * D];
__device__ __half g_h1 [(size_t)MAXROWS * HD];
__device__ __half g_w1 [(size_t)NE * HD * D];   // [E][H][D] transposed fp16
__device__ __half g_w2 [(size_t)NE * D * HD];   // [E][D][H] transposed fp16
__device__ float g_b1f[(size_t)NE * HD];
__device__ float g_y [(size_t)MAXROWS * D];
__device__ float g_wts[MAXROWS];
__device__ int   g_sel[MAXROWS];
__device__ int   g_rowmap[MAXROWS];
__device__ int   g_counts[NE];
__device__ int   g_offsets[NE + 1];
__device__ int   g_cursor[NE];

// ---------------- helpers ----------------------------------------------------
__device__ __forceinline__ uint32_t smem_u32(const void* p) {
    uint32_t a;
    asm("{ .reg .u64 t; cvta.to.shared.u64 t, %1; cvt.u32.u64 %0, t; }"
        : "=r"(a) : "l"(p));
    return a;
}
// swizzle: row stride 128B, XOR (row&7)*16 into column bits
#define SWZC(row, col) ((uint32_t)((row) * 128 + ((col) ^ (((row) & 7) * 16))))

#define CPASYNC16(dst, src) \
    asm volatile("cp.async.cg.shared.global [%0], [%1], 16;" \
                 :: "r"(dst), "l"(src))
#define CP_COMMIT() asm volatile("cp.async.commit_group;")

__device__ __forceinline__ void cp_wait_lead(int lead) {
    if (lead >= 4)      asm volatile("cp.async.wait_group 4;");
    else if (lead == 3) asm volatile("cp.async.wait_group 3;");
    else if (lead == 2) asm volatile("cp.async.wait_group 2;");
    else if (lead == 1) asm volatile("cp.async.wait_group 1;");
    else                asm volatile("cp.async.wait_group 0;");
}

#define LDM4(r0, r1, r2, r3, addr) \
    asm volatile("ldmatrix.sync.aligned.m8n8.x4.shared.b16 {%0,%1,%2,%3}, [%4];" \
        : "=r"(r0), "=r"(r1), "=r"(r2), "=r"(r3) : "r"(addr))

#define MMA16816(c, a, b) \
    asm volatile("mma.sync.aligned.m16n8k16.row.col.f32.f16.f16.f32 " \
        "{%0,%1,%2,%3}, {%4,%5,%6,%7}, {%8,%9}, {%0,%1,%2,%3};" \
        : "+f"((c)[0]), "+f"((c)[1]), "+f"((c)[2]), "+f"((c)[3]) \
        : "r"((a)[0]), "r"((a)[1]), "r"((a)[2]), "r"((a)[3]), \
          "r"((b)[0]), "r"((b)[1]))

__device__ __forceinline__ uint32_t pack_h2(float a, float b) {
    __half2 h = __floats2half2_rn(a, b);
    return *reinterpret_cast<uint32_t*>(&h);
}

// ---------------- weight transpose + fp16 convert (+ optional scale fold) ----
// W: [E][KD][NH] fp32 -> [E][NH][KD] fp16 (k contiguous)
__global__ __launch_bounds__(1024) void convw_kernel(
    const float* __restrict__ W, const float* __restrict__ scale,
    __half* __restrict__ oh, int KD, int NH)
{
    __shared__ float tile[32][33];
    const int e = blockIdx.z;
    const int dr = blockIdx.x * 32 + threadIdx.y;
    const int hr = blockIdx.y * 32 + threadIdx.x;
    tile[threadIdx.y][threadIdx.x] = W[((size_t)e * KD + dr) * NH + hr];
    __syncthreads();
    const int hw = blockIdx.y * 32 + threadIdx.y;
    const int dw = blockIdx.x * 32 + threadIdx.x;
    float v = tile[threadIdx.x][threadIdx.y];
    if (scale) v *= scale[(size_t)e * KD + dw];
    oh[((size_t)e * NH + hw) * KD + dw] = __float2half_rn(v);
}

// b1'[e][h] = b1[e][h] + sum_d ln_bias[e][d] * W1[e][d][h]   (deterministic)
__global__ __launch_bounds__(256) void foldb1_kernel(
    const float* __restrict__ w1, const float* __restrict__ b1,
    const float* __restrict__ lnb)
{
    const int e = blockIdx.y;
    const int h = blockIdx.x * 256 + threadIdx.x;
    float acc = 0.f;
    const float* wp = w1 + (size_t)e * D * HD + h;
    const float* bp = lnb + (size_t)e * D;
    for (int d = 0; d < D; d++) acc = fmaf(bp[d], wp[(size_t)d * HD], acc);
    g_b1f[(size_t)e * HD + h] = b1[(size_t)e * HD + h] + acc;
}

// ---------------- routing ----------------------------------------------------
__global__ void init_kernel() {
    if (threadIdx.x < NE) g_counts[threadIdx.x] = 0;
}

__global__ __launch_bounds__(256) void gate_ln_kernel(
    const float* __restrict__ x, const float* __restrict__ gw)
{
    const int t   = blockIdx.x;
    const int tid = threadIdx.x;
    __shared__ float sh_ws[8], sh_wq[8], sh_wl[8][8];
    __shared__ float sh_mu, sh_rstd;

    const float4 xv = reinterpret_cast<const float4*>(x + (size_t)t * D)[tid];
    float s = xv.x + xv.y + xv.z + xv.w;
    float q = xv.x * xv.x + xv.y * xv.y + xv.z * xv.z + xv.w * xv.w;

    float acc[8];
#pragma unroll
    for (int e = 0; e < 8; e++) acc[e] = 0.f;
    const float xs[4] = {xv.x, xv.y, xv.z, xv.w};
#pragma unroll
    for (int j = 0; j < 4; j++) {
        const int d = tid * 4 + j;
        const float4 g0 = *reinterpret_cast<const float4*>(gw + (size_t)d * 8);
        const float4 g1 = *reinterpret_cast<const float4*>(gw + (size_t)d * 8 + 4);
        const float xj = xs[j];
        acc[0] = fmaf(xj, g0.x, acc[0]); acc[1] = fmaf(xj, g0.y, acc[1]);
        acc[2] = fmaf(xj, g0.z, acc[2]); acc[3] = fmaf(xj, g0.w, acc[3]);
        acc[4] = fmaf(xj, g1.x, acc[4]); acc[5] = fmaf(xj, g1.y, acc[5]);
        acc[6] = fmaf(xj, g1.z, acc[6]); acc[7] = fmaf(xj, g1.w, acc[7]);
    }
#pragma unroll
    for (int o = 16; o > 0; o >>= 1) {
        s += __shfl_xor_sync(0xffffffffu, s, o);
        q += __shfl_xor_sync(0xffffffffu, q, o);
#pragma unroll
        for (int e = 0; e < 8; e++)
            acc[e] += __shfl_xor_sync(0xffffffffu, acc[e], o);
    }
    const int wid = tid >> 5, lane = tid & 31;
    if (lane == 0) {
        sh_ws[wid] = s; sh_wq[wid] = q;
#pragma unroll
        for (int e = 0; e < 8; e++) sh_wl[wid][e] = acc[e];
    }
    __syncthreads();

    if (tid == 0) {
        float S = 0.f, Q = 0.f, L[8];
#pragma unroll
        for (int e = 0; e < 8; e++) L[e] = 0.f;
        for (int w = 0; w < 8; w++) {
            S += sh_ws[w]; Q += sh_wq[w];
#pragma unroll
            for (int e = 0; e < 8; e++) L[e] += sh_wl[w][e];
        }
        const float mu = S * (1.f / (float)D);
        float var = Q * (1.f / (float)D) - mu * mu;
        if (var < 0.f) var = 0.f;
        sh_mu = mu; sh_rstd = rsqrtf(var + LN_EPS);

        float mx = L[0];
#pragma unroll
        for (int e = 1; e < 8; e++) mx = fmaxf(mx, L[e]);
        float p[8], se = 0.f;
#pragma unroll
        for (int e = 0; e < 8; e++) { p[e] = expf(L[e] - mx); se += p[e]; }
        const float inv = 1.f / se;
#pragma unroll
        for (int e = 0; e < 8; e++) p[e] *= inv;

        int i0 = 0; float p0 = p[0];
#pragma unroll
        for (int e = 1; e < 8; e++) if (p[e] > p0) { p0 = p[e]; i0 = e; }
        int i1 = -1; float p1 = -1e30f;
#pragma unroll
        for (int e = 0; e < 8; e++)
            if (e != i0 && p[e] > p1) { p1 = p[e]; i1 = e; }

        const float ew = expf(p1 - p0);
        g_sel[2 * t] = i0;  g_sel[2 * t + 1] = i1;
        g_wts[2 * t] = 1.f / (1.f + ew);
        g_wts[2 * t + 1] = ew / (1.f + ew);
        atomicAdd(&g_counts[i0], 1);
        atomicAdd(&g_counts[i1], 1);
    }
    __syncthreads();

    const float mu = sh_mu, rstd = sh_rstd;
    uint32_t* o = reinterpret_cast<uint32_t*>(g_xn + (size_t)t * D);
    o[tid * 2]     = pack_h2((xv.x - mu) * rstd, (xv.y - mu) * rstd);
    o[tid * 2 + 1] = pack_h2((xv.z - mu) * rstd, (xv.w - mu) * rstd);
}

__global__ void offsets_kernel() {
    if (threadIdx.x == 0) {
        int o = 0;
        for (int e = 0; e < NE; e++) {
            g_offsets[e] = o; g_cursor[e] = o; o += g_counts[e];
        }
        g_offsets[NE] = o;
    }
}

__global__ void scatter_kernel(int total) {
    const int i = blockIdx.x * blockDim.x + threadIdx.x;
    if (i < total) {
        const int e = g_sel[i];
        const int pos = atomicAdd(&g_cursor[e], 1);
        g_rowmap[pos] = i;
    }
}

// ---------------- cp.async pipelined mma.sync grouped GEMM -------------------
// single-plane fp16 A and B; C = A @ B
// G1: h1[row,:] = gelu(xn[tok] @ (s·W1[e]) + b1'[e])   KTOT=D,  NTOT=HD
// G2: y[slot,:] = wts[slot] * (h1[row,:] @ W2[e] + b2[e])
template<bool G1>
__global__ __launch_bounds__(NTH, 1) void gemm_cp(
    const float* __restrict__ bias)
{
    constexpr int KTOT = G1 ? D : HD;
    constexpr int NTOT = G1 ? HD : D;
    constexpr int NC   = KTOT / KC;

    const int e    = blockIdx.z;
    const int seg0 = g_offsets[e];
    const int nseg = g_offsets[e + 1] - seg0;
    const int m0   = blockIdx.y * TM;
    if (m0 >= nseg) return;
    const int n0   = blockIdx.x * TN;

    extern __shared__ __align__(1024) char smem[];
    const uint32_t sb = smem_u32(smem);
    const int tid = threadIdx.x;

    // copy mapping: row = tid>>2, 2x16B at byte (tid&3)*32
    const int crow = tid >> 2;
    const int ck   = (tid & 3) * 16;
    const bool cval = (m0 + crow) < nseg;
    int arow;
    if (G1) arow = cval ? (g_rowmap[seg0 + m0 + crow] >> 1) : 0;
    else    arow = cval ? (seg0 + m0 + crow) : 0;
    const __half* srcA =
        (G1 ? g_xn + (size_t)arow * D : g_h1 + (size_t)arow * HD) + ck;
    const __half* srcB =
        (G1 ? g_w1 : g_w2) + ((size_t)e * NTOT + n0 + crow) * KTOT + ck;

    const uint32_t dst0 = SWZC(crow, (tid & 3) * 32);
    const uint32_t dst1 = SWZC(crow, (tid & 3) * 32 + 16);

    auto issue = [&](int stage, int c) {
        const uint32_t base = sb + stage * BUFB;
        const int kb = c * KC;
        CPASYNC16(base + 0 * TB + dst0, srcA + kb);
        CPASYNC16(base + 0 * TB + dst1, srcA + kb + 8);
        CPASYNC16(base + 1 * TB + dst0, srcB + kb);
        CPASYNC16(base + 1 * TB + dst1, srcB + kb + 8);
        CP_COMMIT();
    };

    // consumer: 16 warps, 32x32 warp tiles
    const int wid    = tid >> 5;
    const int lane   = tid & 31;
    const int warp_m = wid & 3;
    const int warp_n = wid >> 2;

    float acc[2][4][4];
#pragma unroll
    for (int i = 0; i < 2; i++)
#pragma unroll
        for (int j = 0; j < 4; j++)
#pragma unroll
            for (int k = 0; k < 4; k++) acc[i][j][k] = 0.f;

    const uint32_t sel    = (uint32_t)((lane & 7) << 4);
    const uint32_t rowAb  = (uint32_t)((warp_m * 32 + ((lane >> 3) & 1) * 8 + (lane & 7)) * 128);
    const uint32_t colA16 = (uint32_t)((lane >> 4) * 16);
    const uint32_t rowBb  = (uint32_t)((warp_n * 32 + (lane >> 4) * 8 + (lane & 7)) * 128);
    const uint32_t colB16 = (uint32_t)(((lane >> 3) & 1) * 16);

    auto compute = [&](int stage) {
        const uint32_t aB = sb + stage * BUFB;
        const uint32_t bB = aB + TB;
#pragma unroll
        for (int ks = 0; ks < 4; ks++) {
            const uint32_t colA = ((uint32_t)(ks * 32) + colA16) ^ sel;
            const uint32_t colB = ((uint32_t)(ks * 32) + colB16) ^ sel;
            uint32_t ah[2][4], bh[4][2];
#pragma unroll
            for (int i = 0; i < 2; i++)
                LDM4(ah[i][0], ah[i][1], ah[i][2], ah[i][3],
                     aB + rowAb + (uint32_t)(i * 16 * 128) + colA);
#pragma unroll
            for (int j2 = 0; j2 < 2; j2++) {
                uint32_t t0, t1, t2, t3;
                LDM4(t0, t1, t2, t3, bB + rowBb + (uint32_t)(j2 * 16 * 128) + colB);
                bh[2*j2][0]=t0; bh[2*j2][1]=t1; bh[2*j2+1][0]=t2; bh[2*j2+1][1]=t3;
            }
#pragma unroll
            for (int i = 0; i < 2; i++)
#pragma unroll
                for (int j = 0; j < 4; j++) MMA16816(acc[i][j], ah[i], bh[j]);
        }
    };

    // pipeline: 6 stages, 5 in flight
    {
        int p = 0;
        for (; p < NSTAGE - 1 && p < NC; p++) issue(p, p);
    }
    int stage = 0;
    for (int c = 0; c < NC; c++) {
        cp_wait_lead(NC - 1 - c);
        __syncthreads();
        if (c + NSTAGE - 1 < NC) {
            int s = stage + NSTAGE - 1; if (s >= NSTAGE) s -= NSTAGE;
            issue(s, c + NSTAGE - 1);
        }
        compute(stage);
        __syncthreads();
        if (++stage == NSTAGE) stage = 0;
    }

    // epilogue
    {
        const int r4 = lane >> 2;
        const int c2 = 2 * (lane & 3);
        const int nb = n0 + warp_n * 32;
        const float* bp = G1 ? (g_b1f + (size_t)e * NTOT) : (bias + (size_t)e * NTOT);
        float2 bb[4];
#pragma unroll
        for (int j = 0; j < 4; j++)
            bb[j] = *reinterpret_cast<const float2*>(bp + nb + j * 8 + c2);
#pragma unroll
        for (int i = 0; i < 2; i++) {
#pragma unroll
            for (int h = 0; h < 2; h++) {
                const int mloc = warp_m * 32 + i * 16 + h * 8 + r4;
                if (m0 + mloc >= nseg) continue;
                if (G1) {
                    const size_t rb = (size_t)(seg0 + m0 + mloc) * HD + nb;
#pragma unroll
                    for (int j = 0; j < 4; j++) {
                        float y0 = acc[i][j][2*h]   + bb[j].x;
                        float y1 = acc[i][j][2*h+1] + bb[j].y;
                        y0 = 0.5f * y0 * (1.f + erff(y0 * 0.70710678118654752f));
                        y1 = 0.5f * y1 * (1.f + erff(y1 * 0.70710678118654752f));
                        reinterpret_cast<uint32_t*>(g_h1)[(rb + j * 8 + c2) >> 1] =
                            pack_h2(y0, y1);
                    }
                } else {
                    const int slot = g_rowmap[seg0 + m0 + mloc];
                    const float wt = g_wts[slot];
                    float* op = g_y + (size_t)slot * D + nb;
#pragma unroll
                    for (int j = 0; j < 4; j++) {
                        const float y0 = (acc[i][j][2*h]   + bb[j].x) * wt;
                        const float y1 = (acc[i][j][2*h+1] + bb[j].y) * wt;
                        *reinterpret_cast<float2*>(op + j * 8 + c2) = make_float2(y0, y1);
                    }
                }
            }
        }
    }
}

// ---------------- combine ----------------------------------------------------
__global__ void combine_kernel(float* __restrict__ out, int T) {
    const int nd4 = D / 4;
    const int i = blockIdx.x * blockDim.x + threadIdx.x;
    if (i >= T * nd4) return;
    const int t = i / nd4, d4 = i % nd4;
    const float4* y4 = reinterpret_cast<const float4*>(g_y);
    const float4 a = y4[(size_t)(2 * t) * nd4 + d4];
    const float4 b = y4[(size_t)(2 * t + 1) * nd4 + d4];
    reinterpret_cast<float4*>(out)[i] =
        make_float4(a.x + b.x, a.y + b.y, a.z + b.z, a.w + b.w);
}

// ---------------- launch -----------------------------------------------------
extern "C" void kernel_launch(void* const* d_in, const int* in_sizes, int n_in,
                              void* d_out, int out_size)
{
    const float* x   = (const float*)d_in[0];
    const float* gw  = (const float*)d_in[1];
    const float* lns = (const float*)d_in[2];
    const float* lnb = (const float*)d_in[3];
    const float* w1  = (const float*)d_in[4];
    const float* b1  = (const float*)d_in[5];
    const float* w2  = (const float*)d_in[6];
    const float* b2  = (const float*)d_in[7];
    float* out = (float*)d_out;

    const int T = in_sizes[0] / D;
    const int totalRows = T * TOPK;

    cudaFuncSetAttribute(gemm_cp<true>,
                         cudaFuncAttributeMaxDynamicSharedMemorySize, SMEM_BYTES);
    cudaFuncSetAttribute(gemm_cp<false>,
                         cudaFuncAttributeMaxDynamicSharedMemorySize, SMEM_BYTES);

    __half *w1p, *w2p;
    cudaGetSymbolAddress((void**)&w1p, g_w1);
    cudaGetSymbolAddress((void**)&w2p, g_w2);

    dim3 blk32(32, 32);
    convw_kernel<<<dim3(D / 32, HD / 32, NE), blk32>>>(w1, lns, w1p, D, HD);
    convw_kernel<<<dim3(HD / 32, D / 32, NE), blk32>>>(w2, nullptr, w2p, HD, D);
    foldb1_kernel<<<dim3(HD / 256, NE), 256>>>(w1, b1, lnb);

    init_kernel<<<1, 32>>>();
    gate_ln_kernel<<<T, 256>>>(x, gw);
    offsets_kernel<<<1, 32>>>();
    scatter_kernel<<<(totalRows + 255) / 256, 256>>>(totalRows);

    dim3 g1(HD / TN, (totalRows + TM - 1) / TM, NE);
    gemm_cp<true><<<g1, NTH, SMEM_BYTES>>>(nullptr);

    dim3 g2(D / TN, (totalRows + TM - 1) / TM, NE);
    gemm_cp<false><<<g2, NTH, SMEM_BYTES>>>(b2);

    combine_kernel<<<(T * (D / 4) + 255) / 256, 256>>>(out, T);
}